// round 2
// baseline (speedup 1.0000x reference)
#include <cuda_runtime.h>
#include <cstdint>
#include <math.h>

#define HID 2048
#define SLEN 2048
#define NBATCH 2
#define MROWS 4096
#define NHEADS 16
#define HD 128
#define FFD 8192

// ---------------- scratch (device globals; no allocations) ----------------
__device__ float g_mods[NBATCH * 6 * HID];            // [b][i][h]
__device__ float g_xmod[(size_t)MROWS * HID];         // modulated input (then xmod2)
__device__ float g_q[(size_t)MROWS * HID];
__device__ float g_k[(size_t)MROWS * HID];
__device__ float g_v[(size_t)MROWS * HID];
__device__ float g_attn[(size_t)MROWS * HID];
__device__ float g_h2[(size_t)MROWS * HID];           // hidden after first residual
__device__ float g_ff[(size_t)MROWS * 2 * FFD];       // FF1 output (256 MB)
__device__ float g_ffg[(size_t)MROWS * FFD];          // gated FF (128 MB)

// ---------------- helpers ----------------
__device__ __forceinline__ float tf32r(float x) {
    float y;
    asm("cvt.rna.tf32.f32 %0, %1;" : "=f"(y) : "f"(x));
    return y;
}

__device__ __forceinline__ void mma8(float* c, const float* a, const float* b) {
    asm volatile(
        "mma.sync.aligned.m16n8k8.row.col.f32.tf32.tf32.f32 "
        "{%0,%1,%2,%3}, {%4,%5,%6,%7}, {%8,%9}, {%0,%1,%2,%3};\n"
        : "+f"(c[0]), "+f"(c[1]), "+f"(c[2]), "+f"(c[3])
        : "r"(__float_as_uint(a[0])), "r"(__float_as_uint(a[1])),
          "r"(__float_as_uint(a[2])), "r"(__float_as_uint(a[3])),
          "r"(__float_as_uint(b[0])), "r"(__float_as_uint(b[1])));
}

// ---------------- tiny elementwise kernels ----------------
__global__ void k_mods(const float* __restrict__ temb, const float* __restrict__ sst) {
    int i = blockIdx.x * 256 + threadIdx.x;
    if (i >= NBATCH * 6 * HID) return;
    int h = i & (HID - 1);
    int r = i >> 11;            // b*6 + mi
    int b = r / 6, mi = r % 6;
    g_mods[i] = sst[mi * HID + h] + temb[b * HID + h];
}

__global__ void k_xmod1(const float* __restrict__ hidden) {
    int i = blockIdx.x * 256 + threadIdx.x;
    if (i >= MROWS * HID) return;
    int h = i & (HID - 1);
    int b = i >> 22;            // i / (SLEN*HID)
    const float* md = g_mods + b * 6 * HID;
    g_xmod[i] = hidden[i] * (1.f + md[1 * HID + h]) + md[0 * HID + h];
}

__global__ void k_geglu() {
    int i = blockIdx.x * 256 + threadIdx.x;
    if (i >= MROWS * FFD) return;
    int m = i >> 13;            // /8192
    int f = i & (FFD - 1);
    float a = g_ff[(size_t)m * (2 * FFD) + f];
    float g = g_ff[(size_t)m * (2 * FFD) + FFD + f];
    float gl = 0.5f * g * (1.f + tanhf(0.7978845608028654f * (g + 0.044715f * g * g * g)));
    g_ffg[i] = a * gl;
}

// Per-head LayerNorm over contiguous 128-float vectors; one warp per vector.
// `mul` folds the attention softmax scale into q.
__global__ void k_ln_heads(float* __restrict__ X, float mul) {
    int vec = blockIdx.x * 8 + (threadIdx.x >> 5);
    int lane = threadIdx.x & 31;
    float4* p = reinterpret_cast<float4*>(X) + (size_t)vec * 32 + lane;
    float4 v = *p;
    float s = v.x + v.y + v.z + v.w;
    #pragma unroll
    for (int o = 16; o; o >>= 1) s += __shfl_xor_sync(0xffffffffu, s, o);
    float mean = s * (1.f / 128.f);
    float dx = v.x - mean, dy = v.y - mean, dz = v.z - mean, dw = v.w - mean;
    float q = dx * dx + dy * dy + dz * dz + dw * dw;
    #pragma unroll
    for (int o = 16; o; o >>= 1) q += __shfl_xor_sync(0xffffffffu, q, o);
    float r = rsqrtf(q * (1.f / 128.f) + 1e-5f) * mul;
    v.x = dx * r; v.y = dy * r; v.z = dz * r; v.w = dw * r;
    *p = v;
}

// ---------------- tf32 GEMM: C[M,N] = A[M,K] @ W[N,K]^T + bias, with epilogues ----------------
// EPI 0: plain + bias -> C
// EPI 1: attn out-proj: h2 = resid + gate_msa*(v); writes g_h2 and g_xmod (mlp modulation)
// EPI 2: plain + bias -> C  (FF1)
// EPI 3: final: C = resid + gate_mlp*(v)
template <int EPI>
__global__ __launch_bounds__(256, 1) void gemm_tf32(
    const float* __restrict__ A, const float* __restrict__ W,
    const float* __restrict__ bias, float* __restrict__ C,
    int M, int N, int K, const float* __restrict__ resid)
{
    __shared__ float As[128][36];
    __shared__ float Bs[128][36];
    const int tid = threadIdx.x;
    const int bm = blockIdx.y, bn = blockIdx.x;
    const int warp = tid >> 5, lane = tid & 31;
    const int wm = warp >> 2, wn = warp & 3;   // 2 x 4 warp grid
    const int lg = lane >> 2, lt = lane & 3;

    float acc[4][4][4];
    #pragma unroll
    for (int i = 0; i < 4; i++)
        #pragma unroll
        for (int j = 0; j < 4; j++)
            #pragma unroll
            for (int r = 0; r < 4; r++) acc[i][j][r] = 0.f;

    const float* Ab = A + (size_t)(bm * 128) * K;
    const float* Wb = W + (size_t)(bn * 128) * K;

    for (int kt = 0; kt < K; kt += 32) {
        __syncthreads();
        #pragma unroll
        for (int it = 0; it < 4; it++) {
            int idx = tid + it * 256;                 // 0..1023
            int r = idx >> 3, c4 = (idx & 7) << 2;
            float4 va = *reinterpret_cast<const float4*>(Ab + (size_t)r * K + kt + c4);
            As[r][c4 + 0] = tf32r(va.x); As[r][c4 + 1] = tf32r(va.y);
            As[r][c4 + 2] = tf32r(va.z); As[r][c4 + 3] = tf32r(va.w);
            float4 vb = *reinterpret_cast<const float4*>(Wb + (size_t)r * K + kt + c4);
            Bs[r][c4 + 0] = tf32r(vb.x); Bs[r][c4 + 1] = tf32r(vb.y);
            Bs[r][c4 + 2] = tf32r(vb.z); Bs[r][c4 + 3] = tf32r(vb.w);
        }
        __syncthreads();
        #pragma unroll
        for (int ks = 0; ks < 4; ks++) {
            const int k0 = ks * 8 + lt;
            float a[4][4], b[4][2];
            #pragma unroll
            for (int mf = 0; mf < 4; mf++) {
                int r = wm * 64 + mf * 16 + lg;
                a[mf][0] = As[r][k0];     a[mf][1] = As[r + 8][k0];
                a[mf][2] = As[r][k0 + 4]; a[mf][3] = As[r + 8][k0 + 4];
            }
            #pragma unroll
            for (int nf = 0; nf < 4; nf++) {
                int n = wn * 32 + nf * 8 + lg;
                b[nf][0] = Bs[n][k0]; b[nf][1] = Bs[n][k0 + 4];
            }
            #pragma unroll
            for (int mf = 0; mf < 4; mf++)
                #pragma unroll
                for (int nf = 0; nf < 4; nf++) mma8(acc[mf][nf], a[mf], b[nf]);
        }
    }

    #pragma unroll
    for (int mf = 0; mf < 4; mf++) {
        #pragma unroll
        for (int nf = 0; nf < 4; nf++) {
            int row0 = bm * 128 + wm * 64 + mf * 16 + lg;
            int col0 = bn * 128 + wn * 32 + nf * 8 + lt * 2;
            #pragma unroll
            for (int rr = 0; rr < 2; rr++) {
                #pragma unroll
                for (int cc = 0; cc < 2; cc++) {
                    int row = row0 + rr * 8, col = col0 + cc;
                    float v = acc[mf][nf][rr * 2 + cc] + bias[col];
                    size_t o = (size_t)row * N + col;
                    if (EPI == 0 || EPI == 2) {
                        C[o] = v;
                    } else if (EPI == 1) {
                        int b = row >> 11;
                        const float* md = g_mods + b * 6 * HID;
                        float h2 = resid[o] + md[2 * HID + col] * v;
                        g_h2[o] = h2;
                        g_xmod[o] = h2 * (1.f + md[4 * HID + col]) + md[3 * HID + col];
                    } else { // EPI == 3
                        int b = row >> 11;
                        C[o] = resid[o] + g_mods[b * 6 * HID + 5 * HID + col] * v;
                    }
                }
            }
        }
    }
}

// ---------------- flash attention (tf32 mma, online softmax) ----------------
// grid: (S/64 q-tiles, B*NHEADS). 128 threads = 4 warps, each warp owns 16 query rows.
#define ATT_SMEM_FLOATS (64 * 132 + 128 * 68 + 64 * 68)

__global__ __launch_bounds__(128, 1) void attn_kernel(
    const float* __restrict__ Q, const float* __restrict__ Kg,
    const float* __restrict__ V, float* __restrict__ Og)
{
    extern __shared__ float sm[];
    float* Qs  = sm;                 // [64][132]
    float* KVs = Qs + 64 * 132;      // K tile [64][132] then V^T [128][68]
    float* Ps  = KVs + 128 * 68;     // [64][68]

    const int tid = threadIdx.x, warp = tid >> 5, lane = tid & 31;
    const int lg = lane >> 2, lt = lane & 3;
    const int qt = blockIdx.x, bh = blockIdx.y;
    const int b = bh >> 4, h = bh & 15;
    const int m_base = warp * 16;

    const size_t base = (size_t)b * SLEN * HID + (size_t)h * HD;
    const float* Qp = Q + base + (size_t)qt * 64 * HID;
    const float* Kp = Kg + base;
    const float* Vp = V + base;

    for (int i = tid; i < 64 * 128; i += 128) {
        int r = i >> 7, d = i & 127;
        Qs[r * 132 + d] = tf32r(Qp[(size_t)r * HID + d]);   // softmax scale pre-folded into Q
    }

    float o[16][4];
    #pragma unroll
    for (int i = 0; i < 16; i++)
        #pragma unroll
        for (int j = 0; j < 4; j++) o[i][j] = 0.f;
    float m0 = -INFINITY, m1 = -INFINITY, l0 = 0.f, l1 = 0.f;

    for (int kt = 0; kt < SLEN / 64; kt++) {
        __syncthreads();   // prev PV done before overwriting KVs
        for (int i = tid; i < 64 * 128; i += 128) {
            int r = i >> 7, d = i & 127;
            KVs[r * 132 + d] = tf32r(Kp[(size_t)(kt * 64 + r) * HID + d]);
        }
        __syncthreads();

        float s_acc[8][4];
        #pragma unroll
        for (int nf = 0; nf < 8; nf++)
            #pragma unroll
            for (int j = 0; j < 4; j++) s_acc[nf][j] = 0.f;

        #pragma unroll
        for (int ks = 0; ks < 16; ks++) {
            const int k0 = ks * 8 + lt;
            const int ar = m_base + lg;
            float a[4];
            a[0] = Qs[ar * 132 + k0];       a[1] = Qs[(ar + 8) * 132 + k0];
            a[2] = Qs[ar * 132 + k0 + 4];   a[3] = Qs[(ar + 8) * 132 + k0 + 4];
            #pragma unroll
            for (int nf = 0; nf < 8; nf++) {
                int n = nf * 8 + lg;
                float bf[2] = { KVs[n * 132 + k0], KVs[n * 132 + k0 + 4] };
                mma8(s_acc[nf], a, bf);
            }
        }

        // ---- online softmax over this 64-key tile ----
        float t0 = -INFINITY, t1 = -INFINITY;
        #pragma unroll
        for (int nf = 0; nf < 8; nf++) {
            t0 = fmaxf(t0, fmaxf(s_acc[nf][0], s_acc[nf][1]));
            t1 = fmaxf(t1, fmaxf(s_acc[nf][2], s_acc[nf][3]));
        }
        t0 = fmaxf(t0, __shfl_xor_sync(0xffffffffu, t0, 1));
        t0 = fmaxf(t0, __shfl_xor_sync(0xffffffffu, t0, 2));
        t1 = fmaxf(t1, __shfl_xor_sync(0xffffffffu, t1, 1));
        t1 = fmaxf(t1, __shfl_xor_sync(0xffffffffu, t1, 2));
        float nm0 = fmaxf(m0, t0), nm1 = fmaxf(m1, t1);
        float al0 = __expf(m0 - nm0), al1 = __expf(m1 - nm1);
        float ps0 = 0.f, ps1 = 0.f;
        #pragma unroll
        for (int nf = 0; nf < 8; nf++) {
            s_acc[nf][0] = __expf(s_acc[nf][0] - nm0);
            s_acc[nf][1] = __expf(s_acc[nf][1] - nm0);
            s_acc[nf][2] = __expf(s_acc[nf][2] - nm1);
            s_acc[nf][3] = __expf(s_acc[nf][3] - nm1);
            ps0 += s_acc[nf][0] + s_acc[nf][1];
            ps1 += s_acc[nf][2] + s_acc[nf][3];
        }
        ps0 += __shfl_xor_sync(0xffffffffu, ps0, 1);
        ps0 += __shfl_xor_sync(0xffffffffu, ps0, 2);
        ps1 += __shfl_xor_sync(0xffffffffu, ps1, 1);
        ps1 += __shfl_xor_sync(0xffffffffu, ps1, 2);
        l0 = l0 * al0 + ps0;  l1 = l1 * al1 + ps1;
        m0 = nm0;  m1 = nm1;
        #pragma unroll
        for (int nf = 0; nf < 16; nf++) {
            o[nf][0] *= al0; o[nf][1] *= al0; o[nf][2] *= al1; o[nf][3] *= al1;
        }

        __syncthreads();   // all warps done reading K tile
        {
            int pr = m_base + lg;
            #pragma unroll
            for (int nf = 0; nf < 8; nf++) {
                int c = nf * 8 + lt * 2;
                Ps[pr * 68 + c]           = tf32r(s_acc[nf][0]);
                Ps[pr * 68 + c + 1]       = tf32r(s_acc[nf][1]);
                Ps[(pr + 8) * 68 + c]     = tf32r(s_acc[nf][2]);
                Ps[(pr + 8) * 68 + c + 1] = tf32r(s_acc[nf][3]);
            }
        }
        for (int i = tid; i < 64 * 128; i += 128) {
            int s = i >> 7, d = i & 127;
            KVs[d * 68 + s] = tf32r(Vp[(size_t)(kt * 64 + s) * HID + d]);  // V^T
        }
        __syncthreads();

        #pragma unroll
        for (int ks = 0; ks < 8; ks++) {
            const int k0 = ks * 8 + lt;
            const int ar = m_base + lg;
            float a[4];
            a[0] = Ps[ar * 68 + k0];       a[1] = Ps[(ar + 8) * 68 + k0];
            a[2] = Ps[ar * 68 + k0 + 4];   a[3] = Ps[(ar + 8) * 68 + k0 + 4];
            #pragma unroll
            for (int nf = 0; nf < 16; nf++) {
                int n = nf * 8 + lg;
                float bf[2] = { KVs[n * 68 + k0], KVs[n * 68 + k0 + 4] };
                mma8(o[nf], a, bf);
            }
        }
    }

    float il0 = 1.f / l0, il1 = 1.f / l1;
    int row0 = qt * 64 + m_base + lg;
    #pragma unroll
    for (int nf = 0; nf < 16; nf++) {
        size_t oi = (size_t)(b * SLEN + row0) * HID + h * HD + nf * 8 + lt * 2;
        Og[oi]                     = o[nf][0] * il0;
        Og[oi + 1]                 = o[nf][1] * il0;
        Og[oi + (size_t)8 * HID]     = o[nf][2] * il1;
        Og[oi + (size_t)8 * HID + 1] = o[nf][3] * il1;
    }
}

// ---------------- launch ----------------
extern "C" void kernel_launch(void* const* d_in, const int* in_sizes, int n_in,
                              void* d_out, int out_size) {
    const float* hidden = (const float*)d_in[0];
    const float* temb   = (const float*)d_in[1];
    const float* Wq = (const float*)d_in[2];  const float* bq = (const float*)d_in[3];
    const float* Wk = (const float*)d_in[4];  const float* bk = (const float*)d_in[5];
    const float* Wv = (const float*)d_in[6];  const float* bv = (const float*)d_in[7];
    const float* Wo = (const float*)d_in[8];  const float* bo = (const float*)d_in[9];
    const float* Wff = (const float*)d_in[10]; const float* bff = (const float*)d_in[11];
    const float* Wfo = (const float*)d_in[12]; const float* bfo = (const float*)d_in[13];
    const float* sst = (const float*)d_in[14];
    float* out = (float*)d_out;

    void *p_xmod, *p_q, *p_k, *p_v, *p_attn, *p_h2, *p_ff, *p_ffg;
    cudaGetSymbolAddress(&p_xmod, g_xmod);
    cudaGetSymbolAddress(&p_q, g_q);
    cudaGetSymbolAddress(&p_k, g_k);
    cudaGetSymbolAddress(&p_v, g_v);
    cudaGetSymbolAddress(&p_attn, g_attn);
    cudaGetSymbolAddress(&p_h2, g_h2);
    cudaGetSymbolAddress(&p_ff, g_ff);
    cudaGetSymbolAddress(&p_ffg, g_ffg);
    float* xmod = (float*)p_xmod;
    float* q = (float*)p_q; float* k = (float*)p_k; float* v = (float*)p_v;
    float* attn = (float*)p_attn; float* h2 = (float*)p_h2;
    float* ff = (float*)p_ff; float* ffg = (float*)p_ffg;

    cudaFuncSetAttribute(attn_kernel, cudaFuncAttributeMaxDynamicSharedMemorySize,
                         ATT_SMEM_FLOATS * 4);

    k_mods<<<(NBATCH * 6 * HID + 255) / 256, 256>>>(temb, sst);
    k_xmod1<<<(MROWS * HID + 255) / 256, 256>>>(hidden);

    dim3 gH(HID / 128, MROWS / 128);                 // 16 x 32
    gemm_tf32<0><<<gH, 256>>>(xmod, Wq, bq, q, MROWS, HID, HID, nullptr);
    gemm_tf32<0><<<gH, 256>>>(xmod, Wk, bk, k, MROWS, HID, HID, nullptr);
    gemm_tf32<0><<<gH, 256>>>(xmod, Wv, bv, v, MROWS, HID, HID, nullptr);

    k_ln_heads<<<(MROWS * NHEADS) / 8, 256>>>(q, 0.08838834764831845f); // 1/sqrt(128)
    k_ln_heads<<<(MROWS * NHEADS) / 8, 256>>>(k, 1.0f);

    attn_kernel<<<dim3(SLEN / 64, NBATCH * NHEADS), 128, ATT_SMEM_FLOATS * 4>>>(q, k, v, attn);

    gemm_tf32<1><<<gH, 256>>>(attn, Wo, bo, h2, MROWS, HID, HID, hidden);

    dim3 gFF(2 * FFD / 128, MROWS / 128);            // 128 x 32
    gemm_tf32<2><<<gFF, 256>>>(xmod, Wff, bff, ff, MROWS, 2 * FFD, HID, nullptr);

    k_geglu<<<(MROWS * FFD + 255) / 256, 256>>>();

    gemm_tf32<3><<<gH, 256>>>(ffg, Wfo, bfo, out, MROWS, HID, FFD, h2);
}

// round 3
// speedup vs baseline: 1.4339x; 1.4339x over previous
#include <cuda_runtime.h>
#include <cstdint>
#include <math.h>

#define HID 2048
#define SLEN 2048
#define NBATCH 2
#define MROWS 4096
#define NHEADS 16
#define HD 128
#define FFD 8192

// ---------------- scratch (device globals; no allocations) ----------------
__device__ float g_mods[NBATCH * 6 * HID];
__device__ float g_xmod[(size_t)MROWS * HID];          // modulated input (tf32-rounded), then xmod2
__device__ float g_q[(size_t)MROWS * HID];
__device__ float g_k[(size_t)MROWS * HID];
__device__ float g_v[(size_t)MROWS * HID];
__device__ float g_attn[(size_t)MROWS * HID];          // rounded
__device__ float g_h2[(size_t)MROWS * HID];            // full-precision residual
__device__ float g_ffg[(size_t)MROWS * FFD];           // gated FF (rounded)
// pre-rounded / rearranged weights
__device__ float g_Wqkv[(size_t)3 * HID * HID];        // rows: Wq | Wk | Wv  (rounded)
__device__ float g_bqkv[3 * HID];
__device__ float g_Wo[(size_t)HID * HID];              // rounded
__device__ float g_Wffp[(size_t)2 * FFD * HID];        // interleaved rows a0,g0,a1,g1,... (rounded)
__device__ float g_bffp[2 * FFD];
__device__ float g_Wfo[(size_t)HID * FFD];             // rounded

// ---------------- helpers ----------------
__device__ __forceinline__ float tf32r(float x) {
    float y;
    asm("cvt.rna.tf32.f32 %0, %1;" : "=f"(y) : "f"(x));
    return y;
}

__device__ __forceinline__ void mma8(float* c, const float* a, const float* b) {
    asm volatile(
        "mma.sync.aligned.m16n8k8.row.col.f32.tf32.tf32.f32 "
        "{%0,%1,%2,%3}, {%4,%5,%6,%7}, {%8,%9}, {%0,%1,%2,%3};\n"
        : "+f"(c[0]), "+f"(c[1]), "+f"(c[2]), "+f"(c[3])
        : "r"(__float_as_uint(a[0])), "r"(__float_as_uint(a[1])),
          "r"(__float_as_uint(a[2])), "r"(__float_as_uint(a[3])),
          "r"(__float_as_uint(b[0])), "r"(__float_as_uint(b[1])));
}

__device__ __forceinline__ void cp16(uint32_t dst, const void* src) {
    asm volatile("cp.async.cg.shared.global [%0], [%1], 16;\n" :: "r"(dst), "l"(src));
}
#define CP_COMMIT() asm volatile("cp.async.commit_group;\n")
#define CP_WAIT2()  asm volatile("cp.async.wait_group 2;\n")

// ---------------- prep / elementwise ----------------
__global__ void k_mods(const float* __restrict__ temb, const float* __restrict__ sst) {
    int i = blockIdx.x * 256 + threadIdx.x;
    if (i >= NBATCH * 6 * HID) return;
    int h = i & (HID - 1);
    int r = i >> 11;
    int b = r / 6, mi = r % 6;
    g_mods[i] = sst[mi * HID + h] + temb[b * HID + h];
}

__global__ void k_xmod1(const float* __restrict__ hidden) {
    int i = blockIdx.x * 256 + threadIdx.x;
    if (i >= MROWS * HID) return;
    int h = i & (HID - 1);
    int b = i >> 22;
    const float* md = g_mods + b * 6 * HID;
    g_xmod[i] = tf32r(hidden[i] * (1.f + md[1 * HID + h]) + md[0 * HID + h]);
}

__global__ void k_prep_qkvw(const float* __restrict__ Wq, const float* __restrict__ Wk,
                            const float* __restrict__ Wv,
                            const float* __restrict__ bq, const float* __restrict__ bk,
                            const float* __restrict__ bv) {
    size_t i = (size_t)blockIdx.x * 256 + threadIdx.x;
    size_t seg_sz = (size_t)HID * HID;
    if (i < 3 * seg_sz) {
        const float* src = (i < seg_sz) ? Wq : (i < 2 * seg_sz) ? Wk : Wv;
        size_t off = i - (i < seg_sz ? 0 : (i < 2 * seg_sz ? seg_sz : 2 * seg_sz));
        g_Wqkv[i] = tf32r(src[off]);
    }
    if (i < 3 * HID) {
        const float* sb = (i < HID) ? bq : (i < 2 * HID) ? bk : bv;
        g_bqkv[i] = sb[i & (HID - 1)];
    }
}

__global__ void k_prep_wo(const float* __restrict__ Wo) {
    size_t i = (size_t)blockIdx.x * 256 + threadIdx.x;
    if (i < (size_t)HID * HID) g_Wo[i] = tf32r(Wo[i]);
}

__global__ void k_prep_ffw(const float* __restrict__ Wff, const float* __restrict__ bff) {
    size_t i = (size_t)blockIdx.x * 256 + threadIdx.x;
    if (i >= (size_t)2 * FFD * HID) return;
    int r = (int)(i >> 11);               // permuted row
    int c = (int)(i & (HID - 1));
    int src = (r & 1) ? (FFD + (r >> 1)) : (r >> 1);
    g_Wffp[i] = tf32r(Wff[(size_t)src * HID + c]);
    if (c == 0) g_bffp[r] = bff[src];
}

__global__ void k_prep_wfo(const float* __restrict__ Wfo) {
    size_t i = (size_t)blockIdx.x * 256 + threadIdx.x;
    if (i < (size_t)HID * FFD) g_Wfo[i] = tf32r(Wfo[i]);
}

// Per-head LayerNorm; one warp per 128-float vector. `mul` folds softmax scale into q.
__global__ void k_ln_heads(float* __restrict__ X, float mul) {
    int vec = blockIdx.x * 8 + (threadIdx.x >> 5);
    int lane = threadIdx.x & 31;
    float4* p = reinterpret_cast<float4*>(X) + (size_t)vec * 32 + lane;
    float4 v = *p;
    float s = v.x + v.y + v.z + v.w;
    #pragma unroll
    for (int o = 16; o; o >>= 1) s += __shfl_xor_sync(0xffffffffu, s, o);
    float mean = s * (1.f / 128.f);
    float dx = v.x - mean, dy = v.y - mean, dz = v.z - mean, dw = v.w - mean;
    float q = dx * dx + dy * dy + dz * dz + dw * dw;
    #pragma unroll
    for (int o = 16; o; o >>= 1) q += __shfl_xor_sync(0xffffffffu, q, o);
    float r = rsqrtf(q * (1.f / 128.f) + 1e-5f) * mul;
    v.x = dx * r; v.y = dy * r; v.z = dz * r; v.w = dw * r;
    *p = v;
}

// ---------------- pipelined tf32 GEMM: C[M,N] = A[M,K] @ W[N,K]^T + bias ----------------
// Tile 128x256, BK=32, 3-stage cp.async pipeline, 256 threads (2x4 warps, 64x64 warp tiles).
// EPI 0: QKV routing -> g_q/g_k/g_v by column segment
// EPI 1: O-proj: g_h2 = resid + gate_msa*v ; g_xmod = round(modulate_mlp(g_h2))
// EPI 2: FF1 + GEGLU (interleaved cols) -> g_ffg (rounded)
// EPI 3: final: C = resid + gate_mlp*v
#define SA_F (128 * 36)
#define SB_F (256 * 36)
#define SSTG (SA_F + SB_F)
#define GEMM_SMEM_BYTES (3 * SSTG * 4)

template <int EPI>
__global__ __launch_bounds__(256, 1) void gemm_pipe(
    const float* __restrict__ A, const float* __restrict__ W,
    const float* __restrict__ bias, float* __restrict__ C,
    int M, int N, int K, const float* __restrict__ resid)
{
    extern __shared__ float sm[];
    const int tid = threadIdx.x;
    const int bm = blockIdx.y, bn = blockIdx.x;
    const int warp = tid >> 5, lane = tid & 31;
    const int wm = warp >> 2, wn = warp & 3;
    const int lg = lane >> 2, lt = lane & 3;
    const uint32_t smem_u = (uint32_t)__cvta_generic_to_shared(sm);

    float acc[4][8][4];
    #pragma unroll
    for (int i = 0; i < 4; i++)
        #pragma unroll
        for (int j = 0; j < 8; j++)
            #pragma unroll
            for (int r = 0; r < 4; r++) acc[i][j][r] = 0.f;

    const float* Ab = A + (size_t)(bm * 128) * K;
    const float* Wb = W + (size_t)(bn * 256) * K;
    const int nk = K >> 5;

    auto load_stage = [&](int kt, int st) {
        const float* Ak = Ab + kt * 32;
        #pragma unroll
        for (int i = 0; i < 4; i++) {
            int c = tid + i * 256;
            int r = c >> 3, c4 = (c & 7) << 2;
            cp16(smem_u + (uint32_t)(st * SSTG + r * 36 + c4) * 4, Ak + (size_t)r * K + c4);
        }
        const float* Wk2 = Wb + kt * 32;
        #pragma unroll
        for (int i = 0; i < 8; i++) {
            int c = tid + i * 256;
            int r = c >> 3, c4 = (c & 7) << 2;
            cp16(smem_u + (uint32_t)(st * SSTG + SA_F + r * 36 + c4) * 4, Wk2 + (size_t)r * K + c4);
        }
        CP_COMMIT();
    };

    load_stage(0, 0);
    load_stage(1, 1);
    load_stage(2, 2);

    int st = 0;
    for (int kt = 0; kt < nk; kt++) {
        CP_WAIT2();
        __syncthreads();
        const float* As = sm + st * SSTG;
        const float* Bs = As + SA_F;
        #pragma unroll
        for (int ks = 0; ks < 4; ks++) {
            const int k0 = ks * 8 + lt;
            float a[4][4];
            #pragma unroll
            for (int mf = 0; mf < 4; mf++) {
                int r = wm * 64 + mf * 16 + lg;
                a[mf][0] = As[r * 36 + k0];       a[mf][1] = As[(r + 8) * 36 + k0];
                a[mf][2] = As[r * 36 + k0 + 4];   a[mf][3] = As[(r + 8) * 36 + k0 + 4];
            }
            float b[8][2];
            #pragma unroll
            for (int nf = 0; nf < 8; nf++) {
                int n = wn * 64 + nf * 8 + lg;
                b[nf][0] = Bs[n * 36 + k0]; b[nf][1] = Bs[n * 36 + k0 + 4];
            }
            #pragma unroll
            for (int mf = 0; mf < 4; mf++)
                #pragma unroll
                for (int nf = 0; nf < 8; nf++) mma8(acc[mf][nf], a[mf], b[nf]);
        }
        __syncthreads();
        if (kt + 3 < nk) load_stage(kt + 3, st);
        else CP_COMMIT();
        st = (st == 2) ? 0 : st + 1;
    }

    // ---------------- epilogue ----------------
    #pragma unroll
    for (int mf = 0; mf < 4; mf++) {
        #pragma unroll
        for (int nf = 0; nf < 8; nf++) {
            int row0 = bm * 128 + wm * 64 + mf * 16 + lg;
            int col0 = bn * 256 + wn * 64 + nf * 8 + lt * 2;
            float b0 = bias[col0], b1 = bias[col0 + 1];
            #pragma unroll
            for (int rr = 0; rr < 2; rr++) {
                int row = row0 + rr * 8;
                float v0 = acc[mf][nf][rr * 2 + 0] + b0;
                float v1 = acc[mf][nf][rr * 2 + 1] + b1;
                if (EPI == 0) {
                    int seg = col0 >> 11;                      // 0:q 1:k 2:v
                    int colr = col0 & (HID - 1);
                    float* dst = (seg == 0) ? g_q : (seg == 1) ? g_k : g_v;
                    size_t o = (size_t)row * HID + colr;
                    dst[o] = v0; dst[o + 1] = v1;
                } else if (EPI == 1) {
                    int b = row >> 11;
                    const float* md = g_mods + b * 6 * HID;
                    size_t o = (size_t)row * HID + col0;
                    float h0 = resid[o]     + md[2 * HID + col0]     * v0;
                    float h1 = resid[o + 1] + md[2 * HID + col0 + 1] * v1;
                    g_h2[o] = h0; g_h2[o + 1] = h1;
                    g_xmod[o]     = tf32r(h0 * (1.f + md[4 * HID + col0])     + md[3 * HID + col0]);
                    g_xmod[o + 1] = tf32r(h1 * (1.f + md[4 * HID + col0 + 1]) + md[3 * HID + col0 + 1]);
                } else if (EPI == 2) {
                    // v0 = linear part, v1 = gate (interleaved weight rows)
                    float g = v1;
                    float gl = 0.5f * g * (1.f + tanhf(0.7978845608028654f * (g + 0.044715f * g * g * g)));
                    int f = (col0 >> 1);
                    g_ffg[(size_t)row * FFD + f] = tf32r(v0 * gl);
                } else { // EPI == 3
                    int b = row >> 11;
                    size_t o = (size_t)row * HID + col0;
                    C[o]     = resid[o]     + g_mods[b * 6 * HID + 5 * HID + col0]     * v0;
                    C[o + 1] = resid[o + 1] + g_mods[b * 6 * HID + 5 * HID + col0 + 1] * v1;
                }
            }
        }
    }
}

// ---------------- flash attention (tf32 mma, online softmax) ----------------
#define ATT_SMEM_FLOATS (64 * 132 + 128 * 68 + 64 * 68)

__global__ __launch_bounds__(128, 1) void attn_kernel(
    const float* __restrict__ Q, const float* __restrict__ Kg,
    const float* __restrict__ V, float* __restrict__ Og)
{
    extern __shared__ float sm[];
    float* Qs  = sm;
    float* KVs = Qs + 64 * 132;
    float* Ps  = KVs + 128 * 68;

    const int tid = threadIdx.x, warp = tid >> 5, lane = tid & 31;
    const int lg = lane >> 2, lt = lane & 3;
    const int qt = blockIdx.x, bh = blockIdx.y;
    const int b = bh >> 4, h = bh & 15;
    const int m_base = warp * 16;

    const size_t base = (size_t)b * SLEN * HID + (size_t)h * HD;
    const float* Qp = Q + base + (size_t)qt * 64 * HID;
    const float* Kp = Kg + base;
    const float* Vp = V + base;

    for (int i = tid; i < 64 * 128; i += 128) {
        int r = i >> 7, d = i & 127;
        Qs[r * 132 + d] = tf32r(Qp[(size_t)r * HID + d]);
    }

    float o[16][4];
    #pragma unroll
    for (int i = 0; i < 16; i++)
        #pragma unroll
        for (int j = 0; j < 4; j++) o[i][j] = 0.f;
    float m0 = -INFINITY, m1 = -INFINITY, l0 = 0.f, l1 = 0.f;

    for (int kt = 0; kt < SLEN / 64; kt++) {
        __syncthreads();
        for (int i = tid; i < 64 * 128; i += 128) {
            int r = i >> 7, d = i & 127;
            KVs[r * 132 + d] = tf32r(Kp[(size_t)(kt * 64 + r) * HID + d]);
        }
        __syncthreads();

        float s_acc[8][4];
        #pragma unroll
        for (int nf = 0; nf < 8; nf++)
            #pragma unroll
            for (int j = 0; j < 4; j++) s_acc[nf][j] = 0.f;

        #pragma unroll
        for (int ks = 0; ks < 16; ks++) {
            const int k0 = ks * 8 + lt;
            const int ar = m_base + lg;
            float a[4];
            a[0] = Qs[ar * 132 + k0];       a[1] = Qs[(ar + 8) * 132 + k0];
            a[2] = Qs[ar * 132 + k0 + 4];   a[3] = Qs[(ar + 8) * 132 + k0 + 4];
            #pragma unroll
            for (int nf = 0; nf < 8; nf++) {
                int n = nf * 8 + lg;
                float bf[2] = { KVs[n * 132 + k0], KVs[n * 132 + k0 + 4] };
                mma8(s_acc[nf], a, bf);
            }
        }

        float t0 = -INFINITY, t1 = -INFINITY;
        #pragma unroll
        for (int nf = 0; nf < 8; nf++) {
            t0 = fmaxf(t0, fmaxf(s_acc[nf][0], s_acc[nf][1]));
            t1 = fmaxf(t1, fmaxf(s_acc[nf][2], s_acc[nf][3]));
        }
        t0 = fmaxf(t0, __shfl_xor_sync(0xffffffffu, t0, 1));
        t0 = fmaxf(t0, __shfl_xor_sync(0xffffffffu, t0, 2));
        t1 = fmaxf(t1, __shfl_xor_sync(0xffffffffu, t1, 1));
        t1 = fmaxf(t1, __shfl_xor_sync(0xffffffffu, t1, 2));
        float nm0 = fmaxf(m0, t0), nm1 = fmaxf(m1, t1);
        float al0 = __expf(m0 - nm0), al1 = __expf(m1 - nm1);
        float ps0 = 0.f, ps1 = 0.f;
        #pragma unroll
        for (int nf = 0; nf < 8; nf++) {
            s_acc[nf][0] = __expf(s_acc[nf][0] - nm0);
            s_acc[nf][1] = __expf(s_acc[nf][1] - nm0);
            s_acc[nf][2] = __expf(s_acc[nf][2] - nm1);
            s_acc[nf][3] = __expf(s_acc[nf][3] - nm1);
            ps0 += s_acc[nf][0] + s_acc[nf][1];
            ps1 += s_acc[nf][2] + s_acc[nf][3];
        }
        ps0 += __shfl_xor_sync(0xffffffffu, ps0, 1);
        ps0 += __shfl_xor_sync(0xffffffffu, ps0, 2);
        ps1 += __shfl_xor_sync(0xffffffffu, ps1, 1);
        ps1 += __shfl_xor_sync(0xffffffffu, ps1, 2);
        l0 = l0 * al0 + ps0;  l1 = l1 * al1 + ps1;
        m0 = nm0;  m1 = nm1;
        #pragma unroll
        for (int nf = 0; nf < 16; nf++) {
            o[nf][0] *= al0; o[nf][1] *= al0; o[nf][2] *= al1; o[nf][3] *= al1;
        }

        __syncthreads();
        {
            int pr = m_base + lg;
            #pragma unroll
            for (int nf = 0; nf < 8; nf++) {
                int c = nf * 8 + lt * 2;
                Ps[pr * 68 + c]           = tf32r(s_acc[nf][0]);
                Ps[pr * 68 + c + 1]       = tf32r(s_acc[nf][1]);
                Ps[(pr + 8) * 68 + c]     = tf32r(s_acc[nf][2]);
                Ps[(pr + 8) * 68 + c + 1] = tf32r(s_acc[nf][3]);
            }
        }
        for (int i = tid; i < 64 * 128; i += 128) {
            int s = i >> 7, d = i & 127;
            KVs[d * 68 + s] = tf32r(Vp[(size_t)(kt * 64 + s) * HID + d]);
        }
        __syncthreads();

        #pragma unroll
        for (int ks = 0; ks < 8; ks++) {
            const int k0 = ks * 8 + lt;
            const int ar = m_base + lg;
            float a[4];
            a[0] = Ps[ar * 68 + k0];       a[1] = Ps[(ar + 8) * 68 + k0];
            a[2] = Ps[ar * 68 + k0 + 4];   a[3] = Ps[(ar + 8) * 68 + k0 + 4];
            #pragma unroll
            for (int nf = 0; nf < 16; nf++) {
                int n = nf * 8 + lg;
                float bf[2] = { KVs[n * 68 + k0], KVs[n * 68 + k0 + 4] };
                mma8(o[nf], a, bf);
            }
        }
    }

    float il0 = 1.f / l0, il1 = 1.f / l1;
    int row0 = qt * 64 + m_base + lg;
    #pragma unroll
    for (int nf = 0; nf < 16; nf++) {
        size_t oi = (size_t)(b * SLEN + row0) * HID + h * HD + nf * 8 + lt * 2;
        Og[oi]                       = tf32r(o[nf][0] * il0);
        Og[oi + 1]                   = tf32r(o[nf][1] * il0);
        Og[oi + (size_t)8 * HID]     = tf32r(o[nf][2] * il1);
        Og[oi + (size_t)8 * HID + 1] = tf32r(o[nf][3] * il1);
    }
}

// ---------------- launch ----------------
extern "C" void kernel_launch(void* const* d_in, const int* in_sizes, int n_in,
                              void* d_out, int out_size) {
    const float* hidden = (const float*)d_in[0];
    const float* temb   = (const float*)d_in[1];
    const float* Wq = (const float*)d_in[2];  const float* bq = (const float*)d_in[3];
    const float* Wk = (const float*)d_in[4];  const float* bk = (const float*)d_in[5];
    const float* Wv = (const float*)d_in[6];  const float* bv = (const float*)d_in[7];
    const float* Wo = (const float*)d_in[8];  const float* bo = (const float*)d_in[9];
    const float* Wff = (const float*)d_in[10]; const float* bff = (const float*)d_in[11];
    const float* Wfo = (const float*)d_in[12]; const float* bfo = (const float*)d_in[13];
    const float* sst = (const float*)d_in[14];
    float* out = (float*)d_out;

    void *p_xmod, *p_q, *p_k, *p_v, *p_attn, *p_h2, *p_ffg;
    void *p_wqkv, *p_bqkv, *p_wo, *p_wffp, *p_bffp, *p_wfo;
    cudaGetSymbolAddress(&p_xmod, g_xmod);
    cudaGetSymbolAddress(&p_q, g_q);
    cudaGetSymbolAddress(&p_k, g_k);
    cudaGetSymbolAddress(&p_v, g_v);
    cudaGetSymbolAddress(&p_attn, g_attn);
    cudaGetSymbolAddress(&p_h2, g_h2);
    cudaGetSymbolAddress(&p_ffg, g_ffg);
    cudaGetSymbolAddress(&p_wqkv, g_Wqkv);
    cudaGetSymbolAddress(&p_bqkv, g_bqkv);
    cudaGetSymbolAddress(&p_wo, g_Wo);
    cudaGetSymbolAddress(&p_wffp, g_Wffp);
    cudaGetSymbolAddress(&p_bffp, g_bffp);
    cudaGetSymbolAddress(&p_wfo, g_Wfo);
    float* xmod = (float*)p_xmod;
    float* q = (float*)p_q; float* k = (float*)p_k; float* v = (float*)p_v;
    float* attn = (float*)p_attn; float* h2 = (float*)p_h2; float* ffg = (float*)p_ffg;

    cudaFuncSetAttribute(attn_kernel, cudaFuncAttributeMaxDynamicSharedMemorySize,
                         ATT_SMEM_FLOATS * 4);
    cudaFuncSetAttribute(gemm_pipe<0>, cudaFuncAttributeMaxDynamicSharedMemorySize, GEMM_SMEM_BYTES);
    cudaFuncSetAttribute(gemm_pipe<1>, cudaFuncAttributeMaxDynamicSharedMemorySize, GEMM_SMEM_BYTES);
    cudaFuncSetAttribute(gemm_pipe<2>, cudaFuncAttributeMaxDynamicSharedMemorySize, GEMM_SMEM_BYTES);
    cudaFuncSetAttribute(gemm_pipe<3>, cudaFuncAttributeMaxDynamicSharedMemorySize, GEMM_SMEM_BYTES);

    // prep
    k_mods<<<(NBATCH * 6 * HID + 255) / 256, 256>>>(temb, sst);
    k_prep_qkvw<<<(int)(((size_t)3 * HID * HID + 255) / 256), 256>>>(Wq, Wk, Wv, bq, bk, bv);
    k_prep_wo<<<(int)(((size_t)HID * HID + 255) / 256), 256>>>(Wo);
    k_prep_ffw<<<(int)(((size_t)2 * FFD * HID + 255) / 256), 256>>>(Wff, bff);
    k_prep_wfo<<<(int)(((size_t)HID * FFD + 255) / 256), 256>>>(Wfo);
    k_xmod1<<<(MROWS * HID + 255) / 256, 256>>>(hidden);

    // fused QKV GEMM: [4096, 6144] = xmod @ Wqkv^T
    gemm_pipe<0><<<dim3(3 * HID / 256, MROWS / 128), 256, GEMM_SMEM_BYTES>>>(
        xmod, (const float*)p_wqkv, (const float*)p_bqkv, nullptr, MROWS, 3 * HID, HID, nullptr);

    k_ln_heads<<<(MROWS * NHEADS) / 8, 256>>>(q, 0.08838834764831845f);
    k_ln_heads<<<(MROWS * NHEADS) / 8, 256>>>(k, 1.0f);

    attn_kernel<<<dim3(SLEN / 64, NBATCH * NHEADS), 128, ATT_SMEM_FLOATS * 4>>>(q, k, v, attn);

    // O-proj + residual + mlp-modulation
    gemm_pipe<1><<<dim3(HID / 256, MROWS / 128), 256, GEMM_SMEM_BYTES>>>(
        attn, (const float*)p_wo, bo, nullptr, MROWS, HID, HID, hidden);

    // FF1 + GEGLU (interleaved)
    gemm_pipe<2><<<dim3(2 * FFD / 256, MROWS / 128), 256, GEMM_SMEM_BYTES>>>(
        xmod, (const float*)p_wffp, (const float*)p_bffp, nullptr, MROWS, 2 * FFD, HID, nullptr);

    // FF2 + final residual
    gemm_pipe<3><<<dim3(HID / 256, MROWS / 128), 256, GEMM_SMEM_BYTES>>>(
        ffg, (const float*)p_wfo, bfo, out, MROWS, HID, FFD, h2);
}

// round 4
// speedup vs baseline: 1.4540x; 1.0140x over previous
#include <cuda_runtime.h>
#include <cstdint>
#include <math.h>

#define HID 2048
#define SLEN 2048
#define NBATCH 2
#define MROWS 4096
#define NHEADS 16
#define HD 128
#define FFD 8192

// ---------------- scratch (device globals; no allocations) ----------------
__device__ float g_mods[NBATCH * 6 * HID];
__device__ float g_xmod[(size_t)MROWS * HID];   // modulated input (tf32-rounded), then xmod2
__device__ float g_q[(size_t)MROWS * HID];
__device__ float g_k[(size_t)MROWS * HID];
__device__ float g_v[(size_t)MROWS * HID];
__device__ float g_attn[(size_t)MROWS * HID];   // rounded
__device__ float g_h2[(size_t)MROWS * HID];     // full-precision residual
__device__ float g_ffg[(size_t)MROWS * FFD];    // gated FF (rounded)

// ---------------- helpers ----------------
__device__ __forceinline__ float tf32r(float x) {
    float y;
    asm("cvt.rna.tf32.f32 %0, %1;" : "=f"(y) : "f"(x));
    return y;
}
__device__ __forceinline__ uint32_t tf32u(uint32_t x) {
    uint32_t r;
    asm("cvt.rna.tf32.f32 %0, %1;" : "=r"(r) : "f"(__uint_as_float(x)));
    return r;
}

__device__ __forceinline__ void mma8(float* c, const float* a, const float* b) {
    asm volatile(
        "mma.sync.aligned.m16n8k8.row.col.f32.tf32.tf32.f32 "
        "{%0,%1,%2,%3}, {%4,%5,%6,%7}, {%8,%9}, {%0,%1,%2,%3};\n"
        : "+f"(c[0]), "+f"(c[1]), "+f"(c[2]), "+f"(c[3])
        : "r"(__float_as_uint(a[0])), "r"(__float_as_uint(a[1])),
          "r"(__float_as_uint(a[2])), "r"(__float_as_uint(a[3])),
          "r"(__float_as_uint(b[0])), "r"(__float_as_uint(b[1])));
}

__device__ __forceinline__ void mma8u(float* c, const uint32_t* a,
                                      uint32_t b0, uint32_t b1) {
    asm volatile(
        "mma.sync.aligned.m16n8k8.row.col.f32.tf32.tf32.f32 "
        "{%0,%1,%2,%3}, {%4,%5,%6,%7}, {%8,%9}, {%0,%1,%2,%3};\n"
        : "+f"(c[0]), "+f"(c[1]), "+f"(c[2]), "+f"(c[3])
        : "r"(a[0]), "r"(a[1]), "r"(a[2]), "r"(a[3]), "r"(b0), "r"(b1));
}

__device__ __forceinline__ void ldsm4(uint32_t& r0, uint32_t& r1, uint32_t& r2,
                                      uint32_t& r3, uint32_t addr) {
    asm volatile("ldmatrix.sync.aligned.m8n8.x4.shared.b16 {%0,%1,%2,%3}, [%4];\n"
                 : "=r"(r0), "=r"(r1), "=r"(r2), "=r"(r3) : "r"(addr));
}

__device__ __forceinline__ void cp16(uint32_t dst, const void* src) {
    asm volatile("cp.async.cg.shared.global [%0], [%1], 16;\n" :: "r"(dst), "l"(src));
}
#define CP_COMMIT() asm volatile("cp.async.commit_group;\n")
#define CP_WAIT2()  asm volatile("cp.async.wait_group 2;\n")

// ---------------- prep / elementwise ----------------
__global__ void k_mods(const float* __restrict__ temb, const float* __restrict__ sst) {
    int i = blockIdx.x * 256 + threadIdx.x;
    if (i >= NBATCH * 6 * HID) return;
    int h = i & (HID - 1);
    int r = i >> 11;
    int b = r / 6, mi = r % 6;
    g_mods[i] = sst[mi * HID + h] + temb[b * HID + h];
}

__global__ void k_xmod1(const float* __restrict__ hidden) {
    int i = blockIdx.x * 256 + threadIdx.x;
    if (i >= MROWS * HID) return;
    int h = i & (HID - 1);
    int b = i >> 22;
    const float* md = g_mods + b * 6 * HID;
    g_xmod[i] = tf32r(hidden[i] * (1.f + md[1 * HID + h]) + md[0 * HID + h]);
}

// Per-head LayerNorm; one warp per 128-float vector. `mul` folds softmax scale into q.
__global__ void k_ln_heads(float* __restrict__ X, float mul) {
    int vec = blockIdx.x * 8 + (threadIdx.x >> 5);
    int lane = threadIdx.x & 31;
    float4* p = reinterpret_cast<float4*>(X) + (size_t)vec * 32 + lane;
    float4 v = *p;
    float s = v.x + v.y + v.z + v.w;
    #pragma unroll
    for (int o = 16; o; o >>= 1) s += __shfl_xor_sync(0xffffffffu, s, o);
    float mean = s * (1.f / 128.f);
    float dx = v.x - mean, dy = v.y - mean, dz = v.z - mean, dw = v.w - mean;
    float q = dx * dx + dy * dy + dz * dz + dw * dw;
    #pragma unroll
    for (int o = 16; o; o >>= 1) q += __shfl_xor_sync(0xffffffffu, q, o);
    float r = rsqrtf(q * (1.f / 128.f) + 1e-5f) * mul;
    v.x = dx * r; v.y = dy * r; v.z = dz * r; v.w = dw * r;
    *p = v;
}

// ---------------- pipelined tf32 GEMM: C[M,N] = A[M,K] @ W[N,K]^T + bias ----------------
// Tile 128x256, BK=32, 3-stage cp.async pipeline, 256 threads (2x4 warps, 64x64 warp tiles).
// ldmatrix.x4 fragment loads; weights tf32-rounded on fragments (A is pre-rounded).
// MODE 0: O-proj  (direct W): g_h2 = resid + gate_msa*v ; g_xmod = round(modulate_mlp)
// MODE 1: QKV     (3 weight ptrs, col-segment routing -> g_q/g_k/g_v)
// MODE 2: FF1     (interleaved row map a0,g0,a1,g1..., GEGLU -> g_ffg)
// MODE 3: FF2     (direct W): C = resid + gate_mlp*v
#define SA_F (128 * 36)
#define SB_F (256 * 36)
#define SSTG (SA_F + SB_F)
#define SSTGB (SSTG * 4)
#define GEMM_SMEM_BYTES (3 * SSTGB)

template <int MODE>
__global__ __launch_bounds__(256, 1) void gemm_pipe(
    const float* __restrict__ A,
    const float* __restrict__ W0, const float* __restrict__ W1, const float* __restrict__ W2,
    const float* __restrict__ bias0, const float* __restrict__ bias1, const float* __restrict__ bias2,
    float* __restrict__ C, int N, int K, const float* __restrict__ resid)
{
    extern __shared__ float sm[];
    const int tid = threadIdx.x;
    const int bm = blockIdx.y, bn = blockIdx.x;
    const int warp = tid >> 5, lane = tid & 31;
    const int wm = warp >> 2, wn = warp & 3;
    const int lg = lane >> 2, lt = lane & 3;
    const uint32_t smem_u = (uint32_t)__cvta_generic_to_shared(sm);

    // -------- precompute per-thread load pointers (k-invariant) --------
    const float* aptr[4]; uint32_t dA[4];
    #pragma unroll
    for (int i = 0; i < 4; i++) {
        int c = tid + i * 256;
        int r = c >> 3, c4 = (c & 7) << 2;
        aptr[i] = A + (size_t)(bm * 128 + r) * K + c4;
        dA[i] = (uint32_t)(r * 36 + c4) * 4;
    }
    const float* wptr[8]; uint32_t dB[8];
    #pragma unroll
    for (int i = 0; i < 8; i++) {
        int c = tid + i * 256;
        int r = c >> 3, c4 = (c & 7) << 2;
        int R = bn * 256 + r;
        const float* src;
        if (MODE == 1) {
            int seg = R >> 11;
            const float* Wseg = (seg == 0) ? W0 : (seg == 1) ? W1 : W2;
            src = Wseg + (size_t)(R & (HID - 1)) * K;
        } else if (MODE == 2) {
            int sr = (R & 1) ? (FFD + (R >> 1)) : (R >> 1);
            src = W0 + (size_t)sr * K;
        } else {
            src = W0 + (size_t)R * K;
        }
        wptr[i] = src + c4;
        dB[i] = (uint32_t)(SA_F + r * 36 + c4) * 4;
    }

    float acc[4][8][4];
    #pragma unroll
    for (int i = 0; i < 4; i++)
        #pragma unroll
        for (int j = 0; j < 8; j++)
            #pragma unroll
            for (int r = 0; r < 4; r++) acc[i][j][r] = 0.f;

    const int nk = K >> 5;

    auto load_stage = [&](int kt, int st) {
        uint32_t base = smem_u + st * SSTGB;
        #pragma unroll
        for (int i = 0; i < 4; i++) cp16(base + dA[i], aptr[i] + kt * 32);
        #pragma unroll
        for (int i = 0; i < 8; i++) cp16(base + dB[i], wptr[i] + kt * 32);
        CP_COMMIT();
    };

    load_stage(0, 0);
    load_stage(1, 1);
    load_stage(2, 2);

    // lane-dependent ldmatrix base offsets (within a stage)
    const uint32_t aoff = (uint32_t)(((wm * 64 + (lane & 15)) * 36 + ((lane & 16) ? 4 : 0)) * 4);
    const uint32_t boff = (uint32_t)((SA_F + (wn * 64 + (lane & 7) + ((lane & 16) ? 8 : 0)) * 36 +
                                      ((lane & 8) ? 4 : 0)) * 4);

    int st = 0;
    for (int kt = 0; kt < nk; kt++) {
        CP_WAIT2();
        __syncthreads();
        const uint32_t stb = smem_u + st * SSTGB;
        const uint32_t abase = stb + aoff;
        const uint32_t bbase = stb + boff;
        #pragma unroll
        for (int ks = 0; ks < 4; ks++) {
            uint32_t a[4][4];
            #pragma unroll
            for (int mf = 0; mf < 4; mf++)
                ldsm4(a[mf][0], a[mf][1], a[mf][2], a[mf][3],
                      abase + (uint32_t)(mf * 16 * 144 + ks * 32));
            uint32_t b[8][2];
            #pragma unroll
            for (int nf2 = 0; nf2 < 4; nf2++) {
                uint32_t t0, t1, t2, t3;
                ldsm4(t0, t1, t2, t3, bbase + (uint32_t)(nf2 * 16 * 144 + ks * 32));
                b[2 * nf2][0]     = tf32u(t0);
                b[2 * nf2][1]     = tf32u(t1);
                b[2 * nf2 + 1][0] = tf32u(t2);
                b[2 * nf2 + 1][1] = tf32u(t3);
            }
            #pragma unroll
            for (int mf = 0; mf < 4; mf++)
                #pragma unroll
                for (int nf = 0; nf < 8; nf++)
                    mma8u(acc[mf][nf], a[mf], b[nf][0], b[nf][1]);
        }
        __syncthreads();
        if (kt + 3 < nk) load_stage(kt + 3, st);
        else CP_COMMIT();
        st = (st == 2) ? 0 : st + 1;
    }

    // ---------------- epilogue ----------------
    #pragma unroll
    for (int mf = 0; mf < 4; mf++) {
        #pragma unroll
        for (int nf = 0; nf < 8; nf++) {
            int row0 = bm * 128 + wm * 64 + mf * 16 + lg;
            int col0 = bn * 256 + wn * 64 + nf * 8 + lt * 2;
            float b0, b1;
            if (MODE == 1) {
                int seg = col0 >> 11;
                const float* bs = (seg == 0) ? bias0 : (seg == 1) ? bias1 : bias2;
                int colr = col0 & (HID - 1);
                b0 = bs[colr]; b1 = bs[colr + 1];
            } else if (MODE == 2) {
                int f = col0 >> 1;
                b0 = bias0[f]; b1 = bias0[FFD + f];
            } else {
                b0 = bias0[col0]; b1 = bias0[col0 + 1];
            }
            #pragma unroll
            for (int rr = 0; rr < 2; rr++) {
                int row = row0 + rr * 8;
                float v0 = acc[mf][nf][rr * 2 + 0] + b0;
                float v1 = acc[mf][nf][rr * 2 + 1] + b1;
                if (MODE == 1) {
                    int seg = col0 >> 11;
                    int colr = col0 & (HID - 1);
                    float* dst = (seg == 0) ? g_q : (seg == 1) ? g_k : g_v;
                    size_t o = (size_t)row * HID + colr;
                    dst[o] = v0; dst[o + 1] = v1;
                } else if (MODE == 0) {
                    int b = row >> 11;
                    const float* md = g_mods + b * 6 * HID;
                    size_t o = (size_t)row * HID + col0;
                    float h0 = resid[o]     + md[2 * HID + col0]     * v0;
                    float h1 = resid[o + 1] + md[2 * HID + col0 + 1] * v1;
                    g_h2[o] = h0; g_h2[o + 1] = h1;
                    g_xmod[o]     = tf32r(h0 * (1.f + md[4 * HID + col0])     + md[3 * HID + col0]);
                    g_xmod[o + 1] = tf32r(h1 * (1.f + md[4 * HID + col0 + 1]) + md[3 * HID + col0 + 1]);
                } else if (MODE == 2) {
                    float g = v1;
                    float gl = 0.5f * g * (1.f + tanhf(0.7978845608028654f * (g + 0.044715f * g * g * g)));
                    int f = col0 >> 1;
                    g_ffg[(size_t)row * FFD + f] = tf32r(v0 * gl);
                } else { // MODE == 3
                    int b = row >> 11;
                    size_t o = (size_t)row * HID + col0;
                    C[o]     = resid[o]     + g_mods[b * 6 * HID + 5 * HID + col0]     * v0;
                    C[o + 1] = resid[o + 1] + g_mods[b * 6 * HID + 5 * HID + col0 + 1] * v1;
                }
            }
        }
    }
}

// ---------------- flash attention (tf32 mma, online softmax) ----------------
#define ATT_SMEM_FLOATS (64 * 132 + 128 * 68 + 64 * 68)

__global__ __launch_bounds__(128, 1) void attn_kernel(
    const float* __restrict__ Q, const float* __restrict__ Kg,
    const float* __restrict__ V, float* __restrict__ Og)
{
    extern __shared__ float sm[];
    float* Qs  = sm;
    float* KVs = Qs + 64 * 132;
    float* Ps  = KVs + 128 * 68;

    const int tid = threadIdx.x, warp = tid >> 5, lane = tid & 31;
    const int lg = lane >> 2, lt = lane & 3;
    const int qt = blockIdx.x, bh = blockIdx.y;
    const int b = bh >> 4, h = bh & 15;
    const int m_base = warp * 16;

    const size_t base = (size_t)b * SLEN * HID + (size_t)h * HD;
    const float* Qp = Q + base + (size_t)qt * 64 * HID;
    const float* Kp = Kg + base;
    const float* Vp = V + base;

    for (int i = tid; i < 64 * 128; i += 128) {
        int r = i >> 7, d = i & 127;
        Qs[r * 132 + d] = tf32r(Qp[(size_t)r * HID + d]);
    }

    float o[16][4];
    #pragma unroll
    for (int i = 0; i < 16; i++)
        #pragma unroll
        for (int j = 0; j < 4; j++) o[i][j] = 0.f;
    float m0 = -INFINITY, m1 = -INFINITY, l0 = 0.f, l1 = 0.f;

    for (int kt = 0; kt < SLEN / 64; kt++) {
        __syncthreads();
        for (int i = tid; i < 64 * 128; i += 128) {
            int r = i >> 7, d = i & 127;
            KVs[r * 132 + d] = tf32r(Kp[(size_t)(kt * 64 + r) * HID + d]);
        }
        __syncthreads();

        float s_acc[8][4];
        #pragma unroll
        for (int nf = 0; nf < 8; nf++)
            #pragma unroll
            for (int j = 0; j < 4; j++) s_acc[nf][j] = 0.f;

        #pragma unroll
        for (int ks = 0; ks < 16; ks++) {
            const int k0 = ks * 8 + lt;
            const int ar = m_base + lg;
            float a[4];
            a[0] = Qs[ar * 132 + k0];       a[1] = Qs[(ar + 8) * 132 + k0];
            a[2] = Qs[ar * 132 + k0 + 4];   a[3] = Qs[(ar + 8) * 132 + k0 + 4];
            #pragma unroll
            for (int nf = 0; nf < 8; nf++) {
                int n = nf * 8 + lg;
                float bf[2] = { KVs[n * 132 + k0], KVs[n * 132 + k0 + 4] };
                mma8(s_acc[nf], a, bf);
            }
        }

        float t0 = -INFINITY, t1 = -INFINITY;
        #pragma unroll
        for (int nf = 0; nf < 8; nf++) {
            t0 = fmaxf(t0, fmaxf(s_acc[nf][0], s_acc[nf][1]));
            t1 = fmaxf(t1, fmaxf(s_acc[nf][2], s_acc[nf][3]));
        }
        t0 = fmaxf(t0, __shfl_xor_sync(0xffffffffu, t0, 1));
        t0 = fmaxf(t0, __shfl_xor_sync(0xffffffffu, t0, 2));
        t1 = fmaxf(t1, __shfl_xor_sync(0xffffffffu, t1, 1));
        t1 = fmaxf(t1, __shfl_xor_sync(0xffffffffu, t1, 2));
        float nm0 = fmaxf(m0, t0), nm1 = fmaxf(m1, t1);
        float al0 = __expf(m0 - nm0), al1 = __expf(m1 - nm1);
        float ps0 = 0.f, ps1 = 0.f;
        #pragma unroll
        for (int nf = 0; nf < 8; nf++) {
            s_acc[nf][0] = __expf(s_acc[nf][0] - nm0);
            s_acc[nf][1] = __expf(s_acc[nf][1] - nm0);
            s_acc[nf][2] = __expf(s_acc[nf][2] - nm1);
            s_acc[nf][3] = __expf(s_acc[nf][3] - nm1);
            ps0 += s_acc[nf][0] + s_acc[nf][1];
            ps1 += s_acc[nf][2] + s_acc[nf][3];
        }
        ps0 += __shfl_xor_sync(0xffffffffu, ps0, 1);
        ps0 += __shfl_xor_sync(0xffffffffu, ps0, 2);
        ps1 += __shfl_xor_sync(0xffffffffu, ps1, 1);
        ps1 += __shfl_xor_sync(0xffffffffu, ps1, 2);
        l0 = l0 * al0 + ps0;  l1 = l1 * al1 + ps1;
        m0 = nm0;  m1 = nm1;
        #pragma unroll
        for (int nf = 0; nf < 16; nf++) {
            o[nf][0] *= al0; o[nf][1] *= al0; o[nf][2] *= al1; o[nf][3] *= al1;
        }

        __syncthreads();
        {
            int pr = m_base + lg;
            #pragma unroll
            for (int nf = 0; nf < 8; nf++) {
                int c = nf * 8 + lt * 2;
                Ps[pr * 68 + c]           = tf32r(s_acc[nf][0]);
                Ps[pr * 68 + c + 1]       = tf32r(s_acc[nf][1]);
                Ps[(pr + 8) * 68 + c]     = tf32r(s_acc[nf][2]);
                Ps[(pr + 8) * 68 + c + 1] = tf32r(s_acc[nf][3]);
            }
        }
        for (int i = tid; i < 64 * 128; i += 128) {
            int s = i >> 7, d = i & 127;
            KVs[d * 68 + s] = tf32r(Vp[(size_t)(kt * 64 + s) * HID + d]);
        }
        __syncthreads();

        #pragma unroll
        for (int ks = 0; ks < 8; ks++) {
            const int k0 = ks * 8 + lt;
            const int ar = m_base + lg;
            float a[4];
            a[0] = Ps[ar * 68 + k0];       a[1] = Ps[(ar + 8) * 68 + k0];
            a[2] = Ps[ar * 68 + k0 + 4];   a[3] = Ps[(ar + 8) * 68 + k0 + 4];
            #pragma unroll
            for (int nf = 0; nf < 16; nf++) {
                int n = nf * 8 + lg;
                float bf[2] = { KVs[n * 68 + k0], KVs[n * 68 + k0 + 4] };
                mma8(o[nf], a, bf);
            }
        }
    }

    float il0 = 1.f / l0, il1 = 1.f / l1;
    int row0 = qt * 64 + m_base + lg;
    #pragma unroll
    for (int nf = 0; nf < 16; nf++) {
        size_t oi = (size_t)(b * SLEN + row0) * HID + h * HD + nf * 8 + lt * 2;
        Og[oi]                       = tf32r(o[nf][0] * il0);
        Og[oi + 1]                   = tf32r(o[nf][1] * il0);
        Og[oi + (size_t)8 * HID]     = tf32r(o[nf][2] * il1);
        Og[oi + (size_t)8 * HID + 1] = tf32r(o[nf][3] * il1);
    }
}

// ---------------- launch ----------------
extern "C" void kernel_launch(void* const* d_in, const int* in_sizes, int n_in,
                              void* d_out, int out_size) {
    const float* hidden = (const float*)d_in[0];
    const float* temb   = (const float*)d_in[1];
    const float* Wq = (const float*)d_in[2];  const float* bq = (const float*)d_in[3];
    const float* Wk = (const float*)d_in[4];  const float* bk = (const float*)d_in[5];
    const float* Wv = (const float*)d_in[6];  const float* bv = (const float*)d_in[7];
    const float* Wo = (const float*)d_in[8];  const float* bo = (const float*)d_in[9];
    const float* Wff = (const float*)d_in[10]; const float* bff = (const float*)d_in[11];
    const float* Wfo = (const float*)d_in[12]; const float* bfo = (const float*)d_in[13];
    const float* sst = (const float*)d_in[14];
    float* out = (float*)d_out;

    void *p_xmod, *p_q, *p_k, *p_v, *p_attn, *p_h2, *p_ffg;
    cudaGetSymbolAddress(&p_xmod, g_xmod);
    cudaGetSymbolAddress(&p_q, g_q);
    cudaGetSymbolAddress(&p_k, g_k);
    cudaGetSymbolAddress(&p_v, g_v);
    cudaGetSymbolAddress(&p_attn, g_attn);
    cudaGetSymbolAddress(&p_h2, g_h2);
    cudaGetSymbolAddress(&p_ffg, g_ffg);
    float* xmod = (float*)p_xmod;
    float* q = (float*)p_q; float* k = (float*)p_k; float* v = (float*)p_v;
    float* attn = (float*)p_attn; float* h2 = (float*)p_h2; float* ffg = (float*)p_ffg;

    cudaFuncSetAttribute(attn_kernel, cudaFuncAttributeMaxDynamicSharedMemorySize,
                         ATT_SMEM_FLOATS * 4);
    cudaFuncSetAttribute(gemm_pipe<0>, cudaFuncAttributeMaxDynamicSharedMemorySize, GEMM_SMEM_BYTES);
    cudaFuncSetAttribute(gemm_pipe<1>, cudaFuncAttributeMaxDynamicSharedMemorySize, GEMM_SMEM_BYTES);
    cudaFuncSetAttribute(gemm_pipe<2>, cudaFuncAttributeMaxDynamicSharedMemorySize, GEMM_SMEM_BYTES);
    cudaFuncSetAttribute(gemm_pipe<3>, cudaFuncAttributeMaxDynamicSharedMemorySize, GEMM_SMEM_BYTES);

    k_mods<<<(NBATCH * 6 * HID + 255) / 256, 256>>>(temb, sst);
    k_xmod1<<<(MROWS * HID + 255) / 256, 256>>>(hidden);

    // fused QKV GEMM: [4096, 6144] = xmod @ [Wq;Wk;Wv]^T  (routing in epilogue)
    gemm_pipe<1><<<dim3(3 * HID / 256, MROWS / 128), 256, GEMM_SMEM_BYTES>>>(
        xmod, Wq, Wk, Wv, bq, bk, bv, nullptr, 3 * HID, HID, nullptr);

    k_ln_heads<<<(MROWS * NHEADS) / 8, 256>>>(q, 0.08838834764831845f);
    k_ln_heads<<<(MROWS * NHEADS) / 8, 256>>>(k, 1.0f);

    attn_kernel<<<dim3(SLEN / 64, NBATCH * NHEADS), 128, ATT_SMEM_FLOATS * 4>>>(q, k, v, attn);

    // O-proj + residual + mlp-modulation
    gemm_pipe<0><<<dim3(HID / 256, MROWS / 128), 256, GEMM_SMEM_BYTES>>>(
        attn, Wo, nullptr, nullptr, bo, nullptr, nullptr, nullptr, HID, HID, hidden);

    // FF1 + GEGLU (row-interleaved weight addressing)
    gemm_pipe<2><<<dim3(2 * FFD / 256, MROWS / 128), 256, GEMM_SMEM_BYTES>>>(
        xmod, Wff, nullptr, nullptr, bff, nullptr, nullptr, nullptr, 2 * FFD, HID, nullptr);

    // FF2 + final residual
    gemm_pipe<3><<<dim3(HID / 256, MROWS / 128), 256, GEMM_SMEM_BYTES>>>(
        ffg, Wfo, nullptr, nullptr, bfo, nullptr, nullptr, out, HID, FFD, h2);
}

// round 7
// speedup vs baseline: 1.5385x; 1.0581x over previous
#include <cuda_runtime.h>
#include <cstdint>
#include <math.h>

#define HID 2048
#define SLEN 2048
#define NBATCH 2
#define MROWS 4096
#define NHEADS 16
#define HD 128
#define FFD 8192

// ---------------- scratch (device globals; no allocations) ----------------
__device__ float g_mods[NBATCH * 6 * HID];
__device__ float g_xmod[(size_t)MROWS * HID];   // modulated input (tf32-rounded), then xmod2
__device__ float g_q[(size_t)MROWS * HID];
__device__ float g_k[(size_t)MROWS * HID];
__device__ float g_v[(size_t)MROWS * HID];
__device__ float g_attn[(size_t)MROWS * HID];   // rounded
__device__ float g_h2[(size_t)MROWS * HID];     // full-precision residual
__device__ float g_ffg[(size_t)MROWS * FFD];    // gated FF (rounded)

// ---------------- helpers ----------------
__device__ __forceinline__ float tf32r(float x) {
    float y;
    asm("cvt.rna.tf32.f32 %0, %1;" : "=f"(y) : "f"(x));
    return y;
}
__device__ __forceinline__ uint32_t tf32u(uint32_t x) {
    uint32_t r;
    asm("cvt.rna.tf32.f32 %0, %1;" : "=r"(r) : "f"(__uint_as_float(x)));
    return r;
}

__device__ __forceinline__ void mma8(float* c, const float* a, const float* b) {
    asm volatile(
        "mma.sync.aligned.m16n8k8.row.col.f32.tf32.tf32.f32 "
        "{%0,%1,%2,%3}, {%4,%5,%6,%7}, {%8,%9}, {%0,%1,%2,%3};\n"
        : "+f"(c[0]), "+f"(c[1]), "+f"(c[2]), "+f"(c[3])
        : "r"(__float_as_uint(a[0])), "r"(__float_as_uint(a[1])),
          "r"(__float_as_uint(a[2])), "r"(__float_as_uint(a[3])),
          "r"(__float_as_uint(b[0])), "r"(__float_as_uint(b[1])));
}

__device__ __forceinline__ void mma8u(float* c, const uint32_t* a,
                                      uint32_t b0, uint32_t b1) {
    asm volatile(
        "mma.sync.aligned.m16n8k8.row.col.f32.tf32.tf32.f32 "
        "{%0,%1,%2,%3}, {%4,%5,%6,%7}, {%8,%9}, {%0,%1,%2,%3};\n"
        : "+f"(c[0]), "+f"(c[1]), "+f"(c[2]), "+f"(c[3])
        : "r"(a[0]), "r"(a[1]), "r"(a[2]), "r"(a[3]), "r"(b0), "r"(b1));
}

__device__ __forceinline__ void ldsm4(uint32_t& r0, uint32_t& r1, uint32_t& r2,
                                      uint32_t& r3, uint32_t addr) {
    asm volatile("ldmatrix.sync.aligned.m8n8.x4.shared.b16 {%0,%1,%2,%3}, [%4];\n"
                 : "=r"(r0), "=r"(r1), "=r"(r2), "=r"(r3) : "r"(addr));
}

__device__ __forceinline__ void cp16(uint32_t dst, const void* src) {
    asm volatile("cp.async.cg.shared.global [%0], [%1], 16;\n" :: "r"(dst), "l"(src));
}
#define CP_COMMIT() asm volatile("cp.async.commit_group;\n")
#define CP_WAIT1()  asm volatile("cp.async.wait_group 1;\n")

// ---------------- prep / elementwise ----------------
__global__ void k_mods(const float* __restrict__ temb, const float* __restrict__ sst) {
    int i = blockIdx.x * 256 + threadIdx.x;
    if (i >= NBATCH * 6 * HID) return;
    int h = i & (HID - 1);
    int r = i >> 11;
    int b = r / 6, mi = r % 6;
    g_mods[i] = sst[mi * HID + h] + temb[b * HID + h];
}

__global__ void k_xmod1(const float* __restrict__ hidden) {
    int i = blockIdx.x * 256 + threadIdx.x;
    if (i >= MROWS * HID) return;
    int h = i & (HID - 1);
    int b = i >> 22;
    const float* md = g_mods + b * 6 * HID;
    g_xmod[i] = tf32r(hidden[i] * (1.f + md[1 * HID + h]) + md[0 * HID + h]);
}

// Per-head LayerNorm; one warp per 128-float vector. `mul` folds softmax scale into q.
__global__ void k_ln_heads(float* __restrict__ X, float mul) {
    int vec = blockIdx.x * 8 + (threadIdx.x >> 5);
    int lane = threadIdx.x & 31;
    float4* p = reinterpret_cast<float4*>(X) + (size_t)vec * 32 + lane;
    float4 v = *p;
    float s = v.x + v.y + v.z + v.w;
    #pragma unroll
    for (int o = 16; o; o >>= 1) s += __shfl_xor_sync(0xffffffffu, s, o);
    float mean = s * (1.f / 128.f);
    float dx = v.x - mean, dy = v.y - mean, dz = v.z - mean, dw = v.w - mean;
    float q = dx * dx + dy * dy + dz * dz + dw * dw;
    #pragma unroll
    for (int o = 16; o; o >>= 1) q += __shfl_xor_sync(0xffffffffu, q, o);
    float r = rsqrtf(q * (1.f / 128.f) + 1e-5f) * mul;
    v.x = dx * r; v.y = dy * r; v.z = dz * r; v.w = dw * r;
    *p = v;
}

// ---------------- pipelined tf32 GEMM: C[M,N] = A[M,K] @ W[N,K]^T + bias ----------------
// Tile 128x128, BK=32, 3-stage cp.async pipeline, 256 threads (2x4 warps, 64x32 warp
// tiles), 2 CTAs/SM, ONE __syncthreads per k-tile.
// MODE 0: O-proj   MODE 1: QKV routing   MODE 2: FF1+GEGLU   MODE 3: FF2+final
#define SA_F (128 * 36)
#define SB_F (128 * 36)
#define SSTG (SA_F + SB_F)
#define SSTGB (SSTG * 4)
#define GEMM_SMEM_BYTES (3 * SSTGB)

template <int MODE>
__global__ __launch_bounds__(256, 2) void gemm_pipe(
    const float* __restrict__ A,
    const float* __restrict__ W0, const float* __restrict__ W1, const float* __restrict__ W2,
    const float* __restrict__ bias0, const float* __restrict__ bias1, const float* __restrict__ bias2,
    float* __restrict__ C, int K, const float* __restrict__ resid)
{
    extern __shared__ float sm[];
    const int tid = threadIdx.x;
    constexpr bool MFAST = (MODE == 1 || MODE == 2);
    const int bm = MFAST ? blockIdx.x : blockIdx.y;
    const int bn = MFAST ? blockIdx.y : blockIdx.x;
    const int warp = tid >> 5, lane = tid & 31;
    const int wm = warp >> 2, wn = warp & 3;   // 2 x 4 warp grid, warp tile 64x32
    const int lg = lane >> 2, lt = lane & 3;
    const uint32_t smem_u = (uint32_t)__cvta_generic_to_shared(sm);

    // -------- per-thread load pointers (k-invariant) --------
    const float* aptr[4]; uint32_t dA[4];
    #pragma unroll
    for (int i = 0; i < 4; i++) {
        int c = tid + i * 256;
        int r = c >> 3, c4 = (c & 7) << 2;
        aptr[i] = A + (size_t)(bm * 128 + r) * K + c4;
        dA[i] = (uint32_t)(r * 36 + c4) * 4;
    }
    const float* wptr[4]; uint32_t dB[4];
    #pragma unroll
    for (int i = 0; i < 4; i++) {
        int c = tid + i * 256;
        int r = c >> 3, c4 = (c & 7) << 2;
        int R = bn * 128 + r;
        const float* src;
        if (MODE == 1) {
            int seg = R >> 11;
            const float* Wseg = (seg == 0) ? W0 : (seg == 1) ? W1 : W2;
            src = Wseg + (size_t)(R & (HID - 1)) * K;
        } else if (MODE == 2) {
            int sr = (R & 1) ? (FFD + (R >> 1)) : (R >> 1);
            src = W0 + (size_t)sr * K;
        } else {
            src = W0 + (size_t)R * K;
        }
        wptr[i] = src + c4;
        dB[i] = (uint32_t)(SA_F + r * 36 + c4) * 4;
    }

    float acc[4][4][4];
    #pragma unroll
    for (int i = 0; i < 4; i++)
        #pragma unroll
        for (int j = 0; j < 4; j++)
            #pragma unroll
            for (int r = 0; r < 4; r++) acc[i][j][r] = 0.f;

    const int nk = K >> 5;

    auto load_stage = [&](int kt, int st) {
        uint32_t base = smem_u + st * SSTGB;
        #pragma unroll
        for (int i = 0; i < 4; i++) cp16(base + dA[i], aptr[i] + kt * 32);
        #pragma unroll
        for (int i = 0; i < 4; i++) cp16(base + dB[i], wptr[i] + kt * 32);
        CP_COMMIT();
    };

    load_stage(0, 0);
    load_stage(1, 1);

    // lane-dependent ldmatrix base offsets (within a stage)
    const uint32_t aoff = (uint32_t)(((wm * 64 + (lane & 15)) * 36 + ((lane & 16) ? 4 : 0)) * 4);
    const uint32_t boff = (uint32_t)((SA_F + (wn * 32 + (lane & 7) + ((lane & 16) ? 8 : 0)) * 36 +
                                      ((lane & 8) ? 4 : 0)) * 4);

    int st = 0;
    for (int kt = 0; kt < nk; kt++) {
        CP_WAIT1();
        __syncthreads();
        if (kt + 2 < nk) {
            int nb = st + 2; if (nb >= 3) nb -= 3;
            load_stage(kt + 2, nb);
        } else {
            CP_COMMIT();
        }
        const uint32_t stb = smem_u + st * SSTGB;
        const uint32_t abase = stb + aoff;
        const uint32_t bbase = stb + boff;
        #pragma unroll
        for (int ks = 0; ks < 4; ks++) {
            uint32_t a[4][4];
            #pragma unroll
            for (int mf = 0; mf < 4; mf++)
                ldsm4(a[mf][0], a[mf][1], a[mf][2], a[mf][3],
                      abase + (uint32_t)(mf * 16 * 144 + ks * 32));
            uint32_t b[4][2];
            #pragma unroll
            for (int nf2 = 0; nf2 < 2; nf2++) {
                uint32_t t0, t1, t2, t3;
                ldsm4(t0, t1, t2, t3, bbase + (uint32_t)(nf2 * 16 * 144 + ks * 32));
                b[2 * nf2][0]     = tf32u(t0);
                b[2 * nf2][1]     = tf32u(t1);
                b[2 * nf2 + 1][0] = tf32u(t2);
                b[2 * nf2 + 1][1] = tf32u(t3);
            }
            #pragma unroll
            for (int mf = 0; mf < 4; mf++)
                #pragma unroll
                for (int nf = 0; nf < 4; nf++)
                    mma8u(acc[mf][nf], a[mf], b[nf][0], b[nf][1]);
        }
        st = (st == 2) ? 0 : st + 1;
    }

    // ---------------- epilogue ----------------
    #pragma unroll
    for (int mf = 0; mf < 4; mf++) {
        #pragma unroll
        for (int nf = 0; nf < 4; nf++) {
            int row0 = bm * 128 + wm * 64 + mf * 16 + lg;
            int col0 = bn * 128 + wn * 32 + nf * 8 + lt * 2;
            float b0, b1;
            if (MODE == 1) {
                int seg = col0 >> 11;
                const float* bs = (seg == 0) ? bias0 : (seg == 1) ? bias1 : bias2;
                int colr = col0 & (HID - 1);
                b0 = bs[colr]; b1 = bs[colr + 1];
            } else if (MODE == 2) {
                int f = col0 >> 1;
                b0 = bias0[f]; b1 = bias0[FFD + f];
            } else {
                b0 = bias0[col0]; b1 = bias0[col0 + 1];
            }
            #pragma unroll
            for (int rr = 0; rr < 2; rr++) {
                int row = row0 + rr * 8;
                float v0 = acc[mf][nf][rr * 2 + 0] + b0;
                float v1 = acc[mf][nf][rr * 2 + 1] + b1;
                if (MODE == 1) {
                    int seg = col0 >> 11;
                    int colr = col0 & (HID - 1);
                    float* dst = (seg == 0) ? g_q : (seg == 1) ? g_k : g_v;
                    size_t o = (size_t)row * HID + colr;
                    dst[o] = v0; dst[o + 1] = v1;
                } else if (MODE == 0) {
                    int b = row >> 11;
                    const float* md = g_mods + b * 6 * HID;
                    size_t o = (size_t)row * HID + col0;
                    float h0 = resid[o]     + md[2 * HID + col0]     * v0;
                    float h1 = resid[o + 1] + md[2 * HID + col0 + 1] * v1;
                    g_h2[o] = h0; g_h2[o + 1] = h1;
                    g_xmod[o]     = tf32r(h0 * (1.f + md[4 * HID + col0])     + md[3 * HID + col0]);
                    g_xmod[o + 1] = tf32r(h1 * (1.f + md[4 * HID + col0 + 1]) + md[3 * HID + col0 + 1]);
                } else if (MODE == 2) {
                    float g = v1;
                    float gl = 0.5f * g * (1.f + tanhf(0.7978845608028654f * (g + 0.044715f * g * g * g)));
                    int f = col0 >> 1;
                    g_ffg[(size_t)row * FFD + f] = tf32r(v0 * gl);
                } else { // MODE == 3
                    int b = row >> 11;
                    size_t o = (size_t)row * HID + col0;
                    C[o]     = resid[o]     + g_mods[b * 6 * HID + 5 * HID + col0]     * v0;
                    C[o + 1] = resid[o + 1] + g_mods[b * 6 * HID + 5 * HID + col0 + 1] * v1;
                }
            }
        }
    }
}

// ---------------- flash attention (tf32 mma, online softmax) ----------------
#define ATT_SMEM_FLOATS (64 * 132 + 128 * 68 + 64 * 68)

__global__ __launch_bounds__(128, 1) void attn_kernel(
    const float* __restrict__ Q, const float* __restrict__ Kg,
    const float* __restrict__ V, float* __restrict__ Og)
{
    extern __shared__ float sm[];
    float* Qs  = sm;
    float* KVs = Qs + 64 * 132;
    float* Ps  = KVs + 128 * 68;

    const int tid = threadIdx.x, warp = tid >> 5, lane = tid & 31;
    const int lg = lane >> 2, lt = lane & 3;
    const int qt = blockIdx.x, bh = blockIdx.y;
    const int b = bh >> 4, h = bh & 15;
    const int m_base = warp * 16;

    const size_t base = (size_t)b * SLEN * HID + (size_t)h * HD;
    const float* Qp = Q + base + (size_t)qt * 64 * HID;
    const float* Kp = Kg + base;
    const float* Vp = V + base;

    for (int i = tid; i < 64 * 128; i += 128) {
        int r = i >> 7, d = i & 127;
        Qs[r * 132 + d] = tf32r(Qp[(size_t)r * HID + d]);
    }

    float o[16][4];
    #pragma unroll
    for (int i = 0; i < 16; i++)
        #pragma unroll
        for (int j = 0; j < 4; j++) o[i][j] = 0.f;
    float m0 = -INFINITY, m1 = -INFINITY, l0 = 0.f, l1 = 0.f;

    for (int kt = 0; kt < SLEN / 64; kt++) {
        __syncthreads();
        for (int i = tid; i < 64 * 128; i += 128) {
            int r = i >> 7, d = i & 127;
            KVs[r * 132 + d] = tf32r(Kp[(size_t)(kt * 64 + r) * HID + d]);
        }
        __syncthreads();

        float s_acc[8][4];
        #pragma unroll
        for (int nf = 0; nf < 8; nf++)
            #pragma unroll
            for (int j = 0; j < 4; j++) s_acc[nf][j] = 0.f;

        #pragma unroll
        for (int ks = 0; ks < 16; ks++) {
            const int k0 = ks * 8 + lt;
            const int ar = m_base + lg;
            float a[4];
            a[0] = Qs[ar * 132 + k0];       a[1] = Qs[(ar + 8) * 132 + k0];
            a[2] = Qs[ar * 132 + k0 + 4];   a[3] = Qs[(ar + 8) * 132 + k0 + 4];
            #pragma unroll
            for (int nf = 0; nf < 8; nf++) {
                int n = nf * 8 + lg;
                float bf[2] = { KVs[n * 132 + k0], KVs[n * 132 + k0 + 4] };
                mma8(s_acc[nf], a, bf);
            }
        }

        float t0 = -INFINITY, t1 = -INFINITY;
        #pragma unroll
        for (int nf = 0; nf < 8; nf++) {
            t0 = fmaxf(t0, fmaxf(s_acc[nf][0], s_acc[nf][1]));
            t1 = fmaxf(t1, fmaxf(s_acc[nf][2], s_acc[nf][3]));
        }
        t0 = fmaxf(t0, __shfl_xor_sync(0xffffffffu, t0, 1));
        t0 = fmaxf(t0, __shfl_xor_sync(0xffffffffu, t0, 2));
        t1 = fmaxf(t1, __shfl_xor_sync(0xffffffffu, t1, 1));
        t1 = fmaxf(t1, __shfl_xor_sync(0xffffffffu, t1, 2));
        float nm0 = fmaxf(m0, t0), nm1 = fmaxf(m1, t1);
        float al0 = __expf(m0 - nm0), al1 = __expf(m1 - nm1);
        float ps0 = 0.f, ps1 = 0.f;
        #pragma unroll
        for (int nf = 0; nf < 8; nf++) {
            s_acc[nf][0] = __expf(s_acc[nf][0] - nm0);
            s_acc[nf][1] = __expf(s_acc[nf][1] - nm0);
            s_acc[nf][2] = __expf(s_acc[nf][2] - nm1);
            s_acc[nf][3] = __expf(s_acc[nf][3] - nm1);
            ps0 += s_acc[nf][0] + s_acc[nf][1];
            ps1 += s_acc[nf][2] + s_acc[nf][3];
        }
        ps0 += __shfl_xor_sync(0xffffffffu, ps0, 1);
        ps0 += __shfl_xor_sync(0xffffffffu, ps0, 2);
        ps1 += __shfl_xor_sync(0xffffffffu, ps1, 1);
        ps1 += __shfl_xor_sync(0xffffffffu, ps1, 2);
        l0 = l0 * al0 + ps0;  l1 = l1 * al1 + ps1;
        m0 = nm0;  m1 = nm1;
        #pragma unroll
        for (int nf = 0; nf < 16; nf++) {
            o[nf][0] *= al0; o[nf][1] *= al0; o[nf][2] *= al1; o[nf][3] *= al1;
        }

        __syncthreads();
        {
            int pr = m_base + lg;
            #pragma unroll
            for (int nf = 0; nf < 8; nf++) {
                int c = nf * 8 + lt * 2;
                Ps[pr * 68 + c]           = tf32r(s_acc[nf][0]);
                Ps[pr * 68 + c + 1]       = tf32r(s_acc[nf][1]);
                Ps[(pr + 8) * 68 + c]     = tf32r(s_acc[nf][2]);
                Ps[(pr + 8) * 68 + c + 1] = tf32r(s_acc[nf][3]);
            }
        }
        for (int i = tid; i < 64 * 128; i += 128) {
            int s = i >> 7, d = i & 127;
            KVs[d * 68 + s] = tf32r(Vp[(size_t)(kt * 64 + s) * HID + d]);
        }
        __syncthreads();

        #pragma unroll
        for (int ks = 0; ks < 8; ks++) {
            const int k0 = ks * 8 + lt;
            const int ar = m_base + lg;
            float a[4];
            a[0] = Ps[ar * 68 + k0];       a[1] = Ps[(ar + 8) * 68 + k0];
            a[2] = Ps[ar * 68 + k0 + 4];   a[3] = Ps[(ar + 8) * 68 + k0 + 4];
            #pragma unroll
            for (int nf = 0; nf < 16; nf++) {
                int n = nf * 8 + lg;
                float bf[2] = { KVs[n * 68 + k0], KVs[n * 68 + k0 + 4] };
                mma8(o[nf], a, bf);
            }
        }
    }

    float il0 = 1.f / l0, il1 = 1.f / l1;
    int row0 = qt * 64 + m_base + lg;
    #pragma unroll
    for (int nf = 0; nf < 16; nf++) {
        size_t oi = (size_t)(b * SLEN + row0) * HID + h * HD + nf * 8 + lt * 2;
        Og[oi]                       = tf32r(o[nf][0] * il0);
        Og[oi + 1]                   = tf32r(o[nf][1] * il0);
        Og[oi + (size_t)8 * HID]     = tf32r(o[nf][2] * il1);
        Og[oi + (size_t)8 * HID + 1] = tf32r(o[nf][3] * il1);
    }
}

// ---------------- launch ----------------
extern "C" void kernel_launch(void* const* d_in, const int* in_sizes, int n_in,
                              void* d_out, int out_size) {
    const float* hidden = (const float*)d_in[0];
    const float* temb   = (const float*)d_in[1];
    const float* Wq = (const float*)d_in[2];  const float* bq = (const float*)d_in[3];
    const float* Wk = (const float*)d_in[4];  const float* bk = (const float*)d_in[5];
    const float* Wv = (const float*)d_in[6];  const float* bv = (const float*)d_in[7];
    const float* Wo = (const float*)d_in[8];  const float* bo = (const float*)d_in[9];
    const float* Wff = (const float*)d_in[10]; const float* bff = (const float*)d_in[11];
    const float* Wfo = (const float*)d_in[12]; const float* bfo = (const float*)d_in[13];
    const float* sst = (const float*)d_in[14];
    float* out = (float*)d_out;

    void *p_xmod, *p_q, *p_k, *p_v, *p_attn, *p_h2, *p_ffg;
    cudaGetSymbolAddress(&p_xmod, g_xmod);
    cudaGetSymbolAddress(&p_q, g_q);
    cudaGetSymbolAddress(&p_k, g_k);
    cudaGetSymbolAddress(&p_v, g_v);
    cudaGetSymbolAddress(&p_attn, g_attn);
    cudaGetSymbolAddress(&p_h2, g_h2);
    cudaGetSymbolAddress(&p_ffg, g_ffg);
    float* xmod = (float*)p_xmod;
    float* q = (float*)p_q; float* k = (float*)p_k; float* v = (float*)p_v;
    float* attn = (float*)p_attn; float* h2 = (float*)p_h2; float* ffg = (float*)p_ffg;

    cudaFuncSetAttribute(attn_kernel, cudaFuncAttributeMaxDynamicSharedMemorySize,
                         ATT_SMEM_FLOATS * 4);
    cudaFuncSetAttribute(gemm_pipe<0>, cudaFuncAttributeMaxDynamicSharedMemorySize, GEMM_SMEM_BYTES);
    cudaFuncSetAttribute(gemm_pipe<1>, cudaFuncAttributeMaxDynamicSharedMemorySize, GEMM_SMEM_BYTES);
    cudaFuncSetAttribute(gemm_pipe<2>, cudaFuncAttributeMaxDynamicSharedMemorySize, GEMM_SMEM_BYTES);
    cudaFuncSetAttribute(gemm_pipe<3>, cudaFuncAttributeMaxDynamicSharedMemorySize, GEMM_SMEM_BYTES);

    k_mods<<<(NBATCH * 6 * HID + 255) / 256, 256>>>(temb, sst);
    k_xmod1<<<(MROWS * HID + 255) / 256, 256>>>(hidden);

    // fused QKV GEMM: [4096, 6144] = xmod @ [Wq;Wk;Wv]^T  (bm-fastest raster)
    gemm_pipe<1><<<dim3(MROWS / 128, 3 * HID / 128), 256, GEMM_SMEM_BYTES>>>(
        xmod, Wq, Wk, Wv, bq, bk, bv, nullptr, HID, nullptr);

    k_ln_heads<<<(MROWS * NHEADS) / 8, 256>>>(q, 0.08838834764831845f);
    k_ln_heads<<<(MROWS * NHEADS) / 8, 256>>>(k, 1.0f);

    attn_kernel<<<dim3(SLEN / 64, NBATCH * NHEADS), 128, ATT_SMEM_FLOATS * 4>>>(q, k, v, attn);

    // O-proj + residual + mlp-modulation (bn-fastest)
    gemm_pipe<0><<<dim3(HID / 128, MROWS / 128), 256, GEMM_SMEM_BYTES>>>(
        attn, Wo, nullptr, nullptr, bo, nullptr, nullptr, nullptr, HID, hidden);

    // FF1 + GEGLU (bm-fastest)
    gemm_pipe<2><<<dim3(MROWS / 128, 2 * FFD / 128), 256, GEMM_SMEM_BYTES>>>(
        xmod, Wff, nullptr, nullptr, bff, nullptr, nullptr, nullptr, HID, nullptr);

    // FF2 + final residual (bn-fastest)
    gemm_pipe<3><<<dim3(HID / 128, MROWS / 128), 256, GEMM_SMEM_BYTES>>>(
        ffg, Wfo, nullptr, nullptr, bfo, nullptr, nullptr, out, FFD, h2);
}

// round 9
// speedup vs baseline: 2.1287x; 1.3836x over previous
#include <cuda_runtime.h>
#include <cuda_fp16.h>
#include <cstdint>
#include <math.h>

#define HID 2048
#define SLEN 2048
#define NBATCH 2
#define MROWS 4096
#define NHEADS 16
#define HD 128
#define FFD 8192

// ---------------- scratch (device globals; no allocations) ----------------
__device__ float g_mods[NBATCH * 6 * HID];
__device__ __half g_xmod16[(size_t)MROWS * HID];    // modulated input fp16 (then xmod2)
__device__ float g_q[(size_t)MROWS * HID];
__device__ float g_k[(size_t)MROWS * HID];
__device__ float g_v[(size_t)MROWS * HID];
__device__ __half g_attn16[(size_t)MROWS * HID];    // attention output fp16
__device__ float g_h2[(size_t)MROWS * HID];         // full-precision residual
__device__ __half g_ffg16[(size_t)MROWS * FFD];     // gated FF fp16
// fp16 weights (pre-routed)
__device__ __half g_w16qkv[(size_t)3 * HID * HID];  // rows: Wq | Wk | Wv
__device__ __half g_w16o[(size_t)HID * HID];
__device__ __half g_w16ff[(size_t)2 * FFD * HID];   // rows interleaved a0,g0,a1,g1,...
__device__ __half g_w16fo[(size_t)HID * FFD];

// ---------------- helpers ----------------
__device__ __forceinline__ float tf32r(float x) {
    float y;
    asm("cvt.rna.tf32.f32 %0, %1;" : "=f"(y) : "f"(x));
    return y;
}

// fp16 mma m16n8k16
__device__ __forceinline__ void mma16(float* c, const uint32_t* a, uint32_t b0, uint32_t b1) {
    asm volatile(
        "mma.sync.aligned.m16n8k16.row.col.f32.f16.f16.f32 "
        "{%0,%1,%2,%3}, {%4,%5,%6,%7}, {%8,%9}, {%0,%1,%2,%3};\n"
        : "+f"(c[0]), "+f"(c[1]), "+f"(c[2]), "+f"(c[3])
        : "r"(a[0]), "r"(a[1]), "r"(a[2]), "r"(a[3]), "r"(b0), "r"(b1));
}

// tf32 mma (attention keeps the tf32 path)
__device__ __forceinline__ void mma8(float* c, const float* a, const float* b) {
    asm volatile(
        "mma.sync.aligned.m16n8k8.row.col.f32.tf32.tf32.f32 "
        "{%0,%1,%2,%3}, {%4,%5,%6,%7}, {%8,%9}, {%0,%1,%2,%3};\n"
        : "+f"(c[0]), "+f"(c[1]), "+f"(c[2]), "+f"(c[3])
        : "r"(__float_as_uint(a[0])), "r"(__float_as_uint(a[1])),
          "r"(__float_as_uint(a[2])), "r"(__float_as_uint(a[3])),
          "r"(__float_as_uint(b[0])), "r"(__float_as_uint(b[1])));
}

__device__ __forceinline__ void ldsm4(uint32_t& r0, uint32_t& r1, uint32_t& r2,
                                      uint32_t& r3, uint32_t addr) {
    asm volatile("ldmatrix.sync.aligned.m8n8.x4.shared.b16 {%0,%1,%2,%3}, [%4];\n"
                 : "=r"(r0), "=r"(r1), "=r"(r2), "=r"(r3) : "r"(addr));
}

__device__ __forceinline__ void cp16(uint32_t dst, const void* src) {
    asm volatile("cp.async.cg.shared.global [%0], [%1], 16;\n" :: "r"(dst), "l"(src));
}
#define CP_COMMIT() asm volatile("cp.async.commit_group;\n")
#define CP_WAIT1()  asm volatile("cp.async.wait_group 1;\n")

__device__ __forceinline__ uint32_t smem_u32(const void* p) {
    return (uint32_t)__cvta_generic_to_shared(p);
}

// ---------------- prep / elementwise ----------------
__global__ void k_mods(const float* __restrict__ temb, const float* __restrict__ sst) {
    int i = blockIdx.x * 256 + threadIdx.x;
    if (i >= NBATCH * 6 * HID) return;
    int h = i & (HID - 1);
    int r = i >> 11;
    int b = r / 6, mi = r % 6;
    g_mods[i] = sst[mi * HID + h] + temb[b * HID + h];
}

__global__ void k_xmod1(const float* __restrict__ hidden) {
    int i = blockIdx.x * 256 + threadIdx.x;
    if (i >= MROWS * HID) return;
    int h = i & (HID - 1);
    int b = i >> 22;
    const float* md = g_mods + b * 6 * HID;
    g_xmod16[i] = __float2half_rn(hidden[i] * (1.f + md[1 * HID + h]) + md[0 * HID + h]);
}

// direct fp32 -> fp16 convert (vectorized)
__global__ void k_w16(const float4* __restrict__ s, __half* __restrict__ d, int n4) {
    int i = blockIdx.x * 256 + threadIdx.x;
    if (i >= n4) return;
    float4 v = s[i];
    __half2* o = reinterpret_cast<__half2*>(d + (size_t)i * 4);
    o[0] = __floats2half2_rn(v.x, v.y);
    o[1] = __floats2half2_rn(v.z, v.w);
}

// FF weight: interleave rows a0,g0,a1,g1,... while converting
__global__ void k_w16ff(const float* __restrict__ Wff) {
    int i = blockIdx.x * 256 + threadIdx.x;        // over (2*FFD*HID)/4
    if (i >= 2 * FFD * (HID / 4)) return;
    int r = i >> 9;                                 // / (HID/4)
    int c4 = (i & 511) << 2;
    int sr = (r & 1) ? (FFD + (r >> 1)) : (r >> 1);
    float4 v = *reinterpret_cast<const float4*>(Wff + (size_t)sr * HID + c4);
    __half2* o = reinterpret_cast<__half2*>(g_w16ff + (size_t)r * HID + c4);
    o[0] = __floats2half2_rn(v.x, v.y);
    o[1] = __floats2half2_rn(v.z, v.w);
}

// Per-head LayerNorm; one warp per 128-float vector. `mul` folds softmax scale into q.
__global__ void k_ln_heads(float* __restrict__ X, float mul) {
    int vec = blockIdx.x * 8 + (threadIdx.x >> 5);
    int lane = threadIdx.x & 31;
    float4* p = reinterpret_cast<float4*>(X) + (size_t)vec * 32 + lane;
    float4 v = *p;
    float s = v.x + v.y + v.z + v.w;
    #pragma unroll
    for (int o = 16; o; o >>= 1) s += __shfl_xor_sync(0xffffffffu, s, o);
    float mean = s * (1.f / 128.f);
    float dx = v.x - mean, dy = v.y - mean, dz = v.z - mean, dw = v.w - mean;
    float q = dx * dx + dy * dy + dz * dz + dw * dw;
    #pragma unroll
    for (int o = 16; o; o >>= 1) q += __shfl_xor_sync(0xffffffffu, q, o);
    float r = rsqrtf(q * (1.f / 128.f) + 1e-5f) * mul;
    v.x = dx * r; v.y = dy * r; v.z = dz * r; v.w = dw * r;
    *p = v;
}

// ---------------- pipelined fp16 GEMM: C[M,N] = A[M,K] @ W[N,K]^T + bias ----------------
// Tile 128x128, BK=64, 3-stage cp.async, 256 threads (2x4 warps, 64x32 warp tiles),
// 2 CTAs/SM, one __syncthreads per k-tile, fp16 m16n8k16 mma, native ldmatrix b16.
// MODE 0: O-proj   MODE 1: QKV routing   MODE 2: FF1+GEGLU   MODE 3: FF2+final
#define ROWB 144                    // 64 fp16 = 128B + 16B pad
#define SA_B (128 * ROWB)           // 18432 B per matrix
#define SSTG2 (2 * SA_B)            // 36864 B per stage
#define GEMM_SMEM_BYTES (3 * SSTG2) // 110592 B

template <int MODE>
__global__ __launch_bounds__(256, 2) void gemm_h(
    const __half* __restrict__ A, const __half* __restrict__ W,
    const float* __restrict__ bias0, const float* __restrict__ bias1,
    const float* __restrict__ bias2,
    float* __restrict__ C, int K, const float* __restrict__ resid)
{
    extern __shared__ char smc[];
    const int tid = threadIdx.x;
    constexpr bool MFAST = (MODE == 1 || MODE == 2);
    const int bm = MFAST ? blockIdx.x : blockIdx.y;
    const int bn = MFAST ? blockIdx.y : blockIdx.x;
    const int warp = tid >> 5, lane = tid & 31;
    const int wm = warp >> 2, wn = warp & 3;   // 2x4 warp grid, warp tile 64x32
    const int lg = lane >> 2, lt = lane & 3;
    const uint32_t smem_u = smem_u32(smc);

    // per-thread load pointers: 4 chunks of 16B for A, 4 for B, per stage
    const __half* aptr[4]; uint32_t dA[4];
    const __half* wptr[4]; uint32_t dB[4];
    #pragma unroll
    for (int i = 0; i < 4; i++) {
        int idx = tid + i * 256;           // 0..1023
        int r = idx >> 3, c8 = (idx & 7) << 3;
        aptr[i] = A + (size_t)(bm * 128 + r) * K + c8;
        dA[i] = (uint32_t)(r * ROWB + (idx & 7) * 16);
        wptr[i] = W + (size_t)(bn * 128 + r) * K + c8;
        dB[i] = (uint32_t)(SA_B + r * ROWB + (idx & 7) * 16);
    }

    float acc[4][4][4];
    #pragma unroll
    for (int i = 0; i < 4; i++)
        #pragma unroll
        for (int j = 0; j < 4; j++)
            #pragma unroll
            for (int r = 0; r < 4; r++) acc[i][j][r] = 0.f;

    const int nk = K >> 6;

    auto load_stage = [&](int kt, int st) {
        uint32_t base = smem_u + st * SSTG2;
        #pragma unroll
        for (int i = 0; i < 4; i++) cp16(base + dA[i], aptr[i] + kt * 64);
        #pragma unroll
        for (int i = 0; i < 4; i++) cp16(base + dB[i], wptr[i] + kt * 64);
        CP_COMMIT();
    };

    load_stage(0, 0);
    load_stage(1, 1);

    // ldmatrix lane-dependent base offsets (within a stage)
    const uint32_t aoff = (uint32_t)((wm * 64 + (lane & 15)) * ROWB + ((lane & 16) ? 16 : 0));
    const uint32_t boff = (uint32_t)(SA_B + (wn * 32 + (lane & 7) + ((lane & 16) ? 8 : 0)) * ROWB +
                                     ((lane & 8) ? 16 : 0));

    int st = 0;
    for (int kt = 0; kt < nk; kt++) {
        CP_WAIT1();
        __syncthreads();
        if (kt + 2 < nk) {
            int nb = st + 2; if (nb >= 3) nb -= 3;
            load_stage(kt + 2, nb);
        } else {
            CP_COMMIT();
        }
        const uint32_t stb = smem_u + st * SSTG2;
        const uint32_t abase = stb + aoff;
        const uint32_t bbase = stb + boff;
        #pragma unroll
        for (int ks = 0; ks < 4; ks++) {            // 4 k-steps of 16
            uint32_t a[4][4];
            #pragma unroll
            for (int mf = 0; mf < 4; mf++)
                ldsm4(a[mf][0], a[mf][1], a[mf][2], a[mf][3],
                      abase + (uint32_t)(mf * 16 * ROWB + ks * 32));
            uint32_t b[4][2];
            #pragma unroll
            for (int nb2 = 0; nb2 < 2; nb2++) {     // each x4 covers 16 n
                uint32_t t0, t1, t2, t3;
                ldsm4(t0, t1, t2, t3, bbase + (uint32_t)(nb2 * 16 * ROWB + ks * 32));
                b[2 * nb2][0]     = t0;  b[2 * nb2][1]     = t1;
                b[2 * nb2 + 1][0] = t2;  b[2 * nb2 + 1][1] = t3;
            }
            #pragma unroll
            for (int mf = 0; mf < 4; mf++)
                #pragma unroll
                for (int nf = 0; nf < 4; nf++)
                    mma16(acc[mf][nf], a[mf], b[nf][0], b[nf][1]);
        }
        st = (st == 2) ? 0 : st + 1;
    }

    // ---------------- epilogue ----------------
    #pragma unroll
    for (int mf = 0; mf < 4; mf++) {
        #pragma unroll
        for (int nf = 0; nf < 4; nf++) {
            int row0 = bm * 128 + wm * 64 + mf * 16 + lg;
            int col0 = bn * 128 + wn * 32 + nf * 8 + lt * 2;
            float b0, b1;
            if (MODE == 1) {
                int seg = col0 >> 11;
                const float* bs = (seg == 0) ? bias0 : (seg == 1) ? bias1 : bias2;
                int colr = col0 & (HID - 1);
                b0 = bs[colr]; b1 = bs[colr + 1];
            } else if (MODE == 2) {
                int f = col0 >> 1;
                b0 = bias0[f]; b1 = bias0[FFD + f];
            } else {
                b0 = bias0[col0]; b1 = bias0[col0 + 1];
            }
            #pragma unroll
            for (int rr = 0; rr < 2; rr++) {
                int row = row0 + rr * 8;
                float v0 = acc[mf][nf][rr * 2 + 0] + b0;
                float v1 = acc[mf][nf][rr * 2 + 1] + b1;
                if (MODE == 1) {
                    int seg = col0 >> 11;
                    int colr = col0 & (HID - 1);
                    float* dst = (seg == 0) ? g_q : (seg == 1) ? g_k : g_v;
                    size_t o = (size_t)row * HID + colr;
                    dst[o] = v0; dst[o + 1] = v1;
                } else if (MODE == 0) {
                    int b = row >> 11;
                    const float* md = g_mods + b * 6 * HID;
                    size_t o = (size_t)row * HID + col0;
                    float h0 = resid[o]     + md[2 * HID + col0]     * v0;
                    float h1 = resid[o + 1] + md[2 * HID + col0 + 1] * v1;
                    g_h2[o] = h0; g_h2[o + 1] = h1;
                    float x0 = h0 * (1.f + md[4 * HID + col0])     + md[3 * HID + col0];
                    float x1 = h1 * (1.f + md[4 * HID + col0 + 1]) + md[3 * HID + col0 + 1];
                    *reinterpret_cast<__half2*>(&g_xmod16[o]) = __floats2half2_rn(x0, x1);
                } else if (MODE == 2) {
                    float g = v1;
                    float gl = 0.5f * g * (1.f + tanhf(0.7978845608028654f * (g + 0.044715f * g * g * g)));
                    int f = col0 >> 1;
                    g_ffg16[(size_t)row * FFD + f] = __float2half_rn(v0 * gl);
                } else { // MODE == 3
                    int b = row >> 11;
                    size_t o = (size_t)row * HID + col0;
                    C[o]     = resid[o]     + g_mods[b * 6 * HID + 5 * HID + col0]     * v0;
                    C[o + 1] = resid[o + 1] + g_mods[b * 6 * HID + 5 * HID + col0 + 1] * v1;
                }
            }
        }
    }
}

// ---------------- flash attention (tf32 mma, online softmax) ----------------
#define ATT_SMEM_FLOATS (64 * 132 + 128 * 68 + 64 * 68)

__global__ __launch_bounds__(128, 1) void attn_kernel(
    const float* __restrict__ Q, const float* __restrict__ Kg,
    const float* __restrict__ V, __half* __restrict__ Og)
{
    extern __shared__ float sm[];
    float* Qs  = sm;
    float* KVs = Qs + 64 * 132;
    float* Ps  = KVs + 128 * 68;

    const int tid = threadIdx.x, warp = tid >> 5, lane = tid & 31;
    const int lg = lane >> 2, lt = lane & 3;
    const int qt = blockIdx.x, bh = blockIdx.y;
    const int b = bh >> 4, h = bh & 15;
    const int m_base = warp * 16;

    const size_t base = (size_t)b * SLEN * HID + (size_t)h * HD;
    const float* Qp = Q + base + (size_t)qt * 64 * HID;
    const float* Kp = Kg + base;
    const float* Vp = V + base;

    for (int i = tid; i < 64 * 128; i += 128) {
        int r = i >> 7, d = i & 127;
        Qs[r * 132 + d] = tf32r(Qp[(size_t)r * HID + d]);
    }

    float o[16][4];
    #pragma unroll
    for (int i = 0; i < 16; i++)
        #pragma unroll
        for (int j = 0; j < 4; j++) o[i][j] = 0.f;
    float m0 = -INFINITY, m1 = -INFINITY, l0 = 0.f, l1 = 0.f;

    for (int kt = 0; kt < SLEN / 64; kt++) {
        __syncthreads();
        for (int i = tid; i < 64 * 128; i += 128) {
            int r = i >> 7, d = i & 127;
            KVs[r * 132 + d] = tf32r(Kp[(size_t)(kt * 64 + r) * HID + d]);
        }
        __syncthreads();

        float s_acc[8][4];
        #pragma unroll
        for (int nf = 0; nf < 8; nf++)
            #pragma unroll
            for (int j = 0; j < 4; j++) s_acc[nf][j] = 0.f;

        #pragma unroll
        for (int ks = 0; ks < 16; ks++) {
            const int k0 = ks * 8 + lt;
            const int ar = m_base + lg;
            float a[4];
            a[0] = Qs[ar * 132 + k0];       a[1] = Qs[(ar + 8) * 132 + k0];
            a[2] = Qs[ar * 132 + k0 + 4];   a[3] = Qs[(ar + 8) * 132 + k0 + 4];
            #pragma unroll
            for (int nf = 0; nf < 8; nf++) {
                int n = nf * 8 + lg;
                float bf[2] = { KVs[n * 132 + k0], KVs[n * 132 + k0 + 4] };
                mma8(s_acc[nf], a, bf);
            }
        }

        float t0 = -INFINITY, t1 = -INFINITY;
        #pragma unroll
        for (int nf = 0; nf < 8; nf++) {
            t0 = fmaxf(t0, fmaxf(s_acc[nf][0], s_acc[nf][1]));
            t1 = fmaxf(t1, fmaxf(s_acc[nf][2], s_acc[nf][3]));
        }
        t0 = fmaxf(t0, __shfl_xor_sync(0xffffffffu, t0, 1));
        t0 = fmaxf(t0, __shfl_xor_sync(0xffffffffu, t0, 2));
        t1 = fmaxf(t1, __shfl_xor_sync(0xffffffffu, t1, 1));
        t1 = fmaxf(t1, __shfl_xor_sync(0xffffffffu, t1, 2));
        float nm0 = fmaxf(m0, t0), nm1 = fmaxf(m1, t1);
        float al0 = __expf(m0 - nm0), al1 = __expf(m1 - nm1);
        float ps0 = 0.f, ps1 = 0.f;
        #pragma unroll
        for (int nf = 0; nf < 8; nf++) {
            s_acc[nf][0] = __expf(s_acc[nf][0] - nm0);
            s_acc[nf][1] = __expf(s_acc[nf][1] - nm0);
            s_acc[nf][2] = __expf(s_acc[nf][2] - nm1);
            s_acc[nf][3] = __expf(s_acc[nf][3] - nm1);
            ps0 += s_acc[nf][0] + s_acc[nf][1];
            ps1 += s_acc[nf][2] + s_acc[nf][3];
        }
        ps0 += __shfl_xor_sync(0xffffffffu, ps0, 1);
        ps0 += __shfl_xor_sync(0xffffffffu, ps0, 2);
        ps1 += __shfl_xor_sync(0xffffffffu, ps1, 1);
        ps1 += __shfl_xor_sync(0xffffffffu, ps1, 2);
        l0 = l0 * al0 + ps0;  l1 = l1 * al1 + ps1;
        m0 = nm0;  m1 = nm1;
        #pragma unroll
        for (int nf = 0; nf < 16; nf++) {
            o[nf][0] *= al0; o[nf][1] *= al0; o[nf][2] *= al1; o[nf][3] *= al1;
        }

        __syncthreads();
        {
            int pr = m_base + lg;
            #pragma unroll
            for (int nf = 0; nf < 8; nf++) {
                int c = nf * 8 + lt * 2;
                Ps[pr * 68 + c]           = tf32r(s_acc[nf][0]);
                Ps[pr * 68 + c + 1]       = tf32r(s_acc[nf][1]);
                Ps[(pr + 8) * 68 + c]     = tf32r(s_acc[nf][2]);
                Ps[(pr + 8) * 68 + c + 1] = tf32r(s_acc[nf][3]);
            }
        }
        for (int i = tid; i < 64 * 128; i += 128) {
            int s = i >> 7, d = i & 127;
            KVs[d * 68 + s] = tf32r(Vp[(size_t)(kt * 64 + s) * HID + d]);
        }
        __syncthreads();

        #pragma unroll
        for (int ks = 0; ks < 8; ks++) {
            const int k0 = ks * 8 + lt;
            const int ar = m_base + lg;
            float a[4];
            a[0] = Ps[ar * 68 + k0];       a[1] = Ps[(ar + 8) * 68 + k0];
            a[2] = Ps[ar * 68 + k0 + 4];   a[3] = Ps[(ar + 8) * 68 + k0 + 4];
            #pragma unroll
            for (int nf = 0; nf < 16; nf++) {
                int n = nf * 8 + lg;
                float bf[2] = { KVs[n * 68 + k0], KVs[n * 68 + k0 + 4] };
                mma8(o[nf], a, bf);
            }
        }
    }

    float il0 = 1.f / l0, il1 = 1.f / l1;
    int row0 = qt * 64 + m_base + lg;
    #pragma unroll
    for (int nf = 0; nf < 16; nf++) {
        size_t oi = (size_t)(b * SLEN + row0) * HID + h * HD + nf * 8 + lt * 2;
        *reinterpret_cast<__half2*>(&Og[oi]) =
            __floats2half2_rn(o[nf][0] * il0, o[nf][1] * il0);
        *reinterpret_cast<__half2*>(&Og[oi + (size_t)8 * HID]) =
            __floats2half2_rn(o[nf][2] * il1, o[nf][3] * il1);
    }
}

// ---------------- launch ----------------
extern "C" void kernel_launch(void* const* d_in, const int* in_sizes, int n_in,
                              void* d_out, int out_size) {
    const float* hidden = (const float*)d_in[0];
    const float* temb   = (const float*)d_in[1];
    const float* Wq = (const float*)d_in[2];  const float* bq = (const float*)d_in[3];
    const float* Wk = (const float*)d_in[4];  const float* bk = (const float*)d_in[5];
    const float* Wv = (const float*)d_in[6];  const float* bv = (const float*)d_in[7];
    const float* Wo = (const float*)d_in[8];  const float* bo = (const float*)d_in[9];
    const float* Wff = (const float*)d_in[10]; const float* bff = (const float*)d_in[11];
    const float* Wfo = (const float*)d_in[12]; const float* bfo = (const float*)d_in[13];
    const float* sst = (const float*)d_in[14];
    float* out = (float*)d_out;

    void *p_xmod, *p_q, *p_k, *p_v, *p_attn, *p_h2, *p_ffg;
    void *p_wqkv, *p_wo, *p_wff, *p_wfo;
    cudaGetSymbolAddress(&p_xmod, g_xmod16);
    cudaGetSymbolAddress(&p_q, g_q);
    cudaGetSymbolAddress(&p_k, g_k);
    cudaGetSymbolAddress(&p_v, g_v);
    cudaGetSymbolAddress(&p_attn, g_attn16);
    cudaGetSymbolAddress(&p_h2, g_h2);
    cudaGetSymbolAddress(&p_ffg, g_ffg16);
    cudaGetSymbolAddress(&p_wqkv, g_w16qkv);
    cudaGetSymbolAddress(&p_wo, g_w16o);
    cudaGetSymbolAddress(&p_wff, g_w16ff);
    cudaGetSymbolAddress(&p_wfo, g_w16fo);
    __half* xmod = (__half*)p_xmod;
    float* q = (float*)p_q; float* k = (float*)p_k; float* v = (float*)p_v;
    __half* attn = (__half*)p_attn; float* h2 = (float*)p_h2; __half* ffg = (__half*)p_ffg;
    __half* wqkv = (__half*)p_wqkv; __half* wo = (__half*)p_wo;
    __half* wff = (__half*)p_wff; __half* wfo = (__half*)p_wfo;

    cudaFuncSetAttribute(attn_kernel, cudaFuncAttributeMaxDynamicSharedMemorySize,
                         ATT_SMEM_FLOATS * 4);
    cudaFuncSetAttribute(gemm_h<0>, cudaFuncAttributeMaxDynamicSharedMemorySize, GEMM_SMEM_BYTES);
    cudaFuncSetAttribute(gemm_h<1>, cudaFuncAttributeMaxDynamicSharedMemorySize, GEMM_SMEM_BYTES);
    cudaFuncSetAttribute(gemm_h<2>, cudaFuncAttributeMaxDynamicSharedMemorySize, GEMM_SMEM_BYTES);
    cudaFuncSetAttribute(gemm_h<3>, cudaFuncAttributeMaxDynamicSharedMemorySize, GEMM_SMEM_BYTES);

    // prep: modulation + fp16 weight conversion (routing baked in)
    k_mods<<<(NBATCH * 6 * HID + 255) / 256, 256>>>(temb, sst);
    k_xmod1<<<(MROWS * HID + 255) / 256, 256>>>(hidden);
    {
        int n4h = HID * HID / 4;
        k_w16<<<n4h / 256, 256>>>((const float4*)Wq, wqkv, n4h);
        k_w16<<<n4h / 256, 256>>>((const float4*)Wk, wqkv + (size_t)HID * HID, n4h);
        k_w16<<<n4h / 256, 256>>>((const float4*)Wv, wqkv + (size_t)2 * HID * HID, n4h);
        k_w16<<<n4h / 256, 256>>>((const float4*)Wo, wo, n4h);
        k_w16ff<<<(2 * FFD * (HID / 4)) / 256, 256>>>(Wff);
        int n4o = HID * FFD / 4;
        k_w16<<<n4o / 256, 256>>>((const float4*)Wfo, wfo, n4o);
    }

    // fused QKV GEMM: [4096, 6144] (bm-fastest raster)
    gemm_h<1><<<dim3(MROWS / 128, 3 * HID / 128), 256, GEMM_SMEM_BYTES>>>(
        xmod, wqkv, bq, bk, bv, nullptr, HID, nullptr);

    k_ln_heads<<<(MROWS * NHEADS) / 8, 256>>>(q, 0.08838834764831845f);
    k_ln_heads<<<(MROWS * NHEADS) / 8, 256>>>(k, 1.0f);

    attn_kernel<<<dim3(SLEN / 64, NBATCH * NHEADS), 128, ATT_SMEM_FLOATS * 4>>>(q, k, v, attn);

    // O-proj + residual + mlp-modulation (bn-fastest)
    gemm_h<0><<<dim3(HID / 128, MROWS / 128), 256, GEMM_SMEM_BYTES>>>(
        attn, wo, bo, nullptr, nullptr, nullptr, HID, hidden);

    // FF1 + GEGLU (bm-fastest)
    gemm_h<2><<<dim3(MROWS / 128, 2 * FFD / 128), 256, GEMM_SMEM_BYTES>>>(
        xmod, wff, bff, nullptr, nullptr, nullptr, HID, nullptr);

    // FF2 + final residual (bn-fastest)
    gemm_h<3><<<dim3(HID / 128, MROWS / 128), 256, GEMM_SMEM_BYTES>>>(
        ffg, wfo, bfo, nullptr, nullptr, out, FFD, h2);
}

// round 10
// speedup vs baseline: 4.3099x; 2.0246x over previous
#include <cuda_runtime.h>
#include <cuda_fp16.h>
#include <cstdint>
#include <math.h>

#define HID 2048
#define SLEN 2048
#define NBATCH 2
#define MROWS 4096
#define NHEADS 16
#define HD 128
#define FFD 8192

// ---------------- scratch (device globals; no allocations) ----------------
__device__ float g_mods[NBATCH * 6 * HID];
__device__ __half g_xmod16[(size_t)MROWS * HID];    // modulated input fp16 (then xmod2)
__device__ __half g_q16[(size_t)MROWS * HID];
__device__ __half g_k16[(size_t)MROWS * HID];
__device__ __half g_v16[(size_t)MROWS * HID];
__device__ __half g_attn16[(size_t)MROWS * HID];    // attention output fp16
__device__ float g_h2[(size_t)MROWS * HID];         // full-precision residual
__device__ __half g_ffg16[(size_t)MROWS * FFD];     // gated FF fp16
// fp16 weights (pre-routed)
__device__ __half g_w16qkv[(size_t)3 * HID * HID];  // rows: Wq | Wk | Wv
__device__ __half g_w16o[(size_t)HID * HID];
__device__ __half g_w16ff[(size_t)2 * FFD * HID];   // rows interleaved a0,g0,a1,g1,...
__device__ __half g_w16fo[(size_t)HID * FFD];

// ---------------- helpers ----------------
// fp16 mma m16n8k16
__device__ __forceinline__ void mma16(float* c, const uint32_t* a, uint32_t b0, uint32_t b1) {
    asm volatile(
        "mma.sync.aligned.m16n8k16.row.col.f32.f16.f16.f32 "
        "{%0,%1,%2,%3}, {%4,%5,%6,%7}, {%8,%9}, {%0,%1,%2,%3};\n"
        : "+f"(c[0]), "+f"(c[1]), "+f"(c[2]), "+f"(c[3])
        : "r"(a[0]), "r"(a[1]), "r"(a[2]), "r"(a[3]), "r"(b0), "r"(b1));
}

__device__ __forceinline__ void ldsm4(uint32_t& r0, uint32_t& r1, uint32_t& r2,
                                      uint32_t& r3, uint32_t addr) {
    asm volatile("ldmatrix.sync.aligned.m8n8.x4.shared.b16 {%0,%1,%2,%3}, [%4];\n"
                 : "=r"(r0), "=r"(r1), "=r"(r2), "=r"(r3) : "r"(addr));
}

__device__ __forceinline__ void ldsm4t(uint32_t& r0, uint32_t& r1, uint32_t& r2,
                                       uint32_t& r3, uint32_t addr) {
    asm volatile("ldmatrix.sync.aligned.m8n8.x4.trans.shared.b16 {%0,%1,%2,%3}, [%4];\n"
                 : "=r"(r0), "=r"(r1), "=r"(r2), "=r"(r3) : "r"(addr));
}

__device__ __forceinline__ void cp16(uint32_t dst, const void* src) {
    asm volatile("cp.async.cg.shared.global [%0], [%1], 16;\n" :: "r"(dst), "l"(src));
}
#define CP_COMMIT() asm volatile("cp.async.commit_group;\n")
#define CP_WAIT1()  asm volatile("cp.async.wait_group 1;\n")
#define CP_COMMIT_WAIT0() asm volatile("cp.async.commit_group;\ncp.async.wait_group 0;\n" ::: "memory")

__device__ __forceinline__ uint32_t smem_u32(const void* p) {
    return (uint32_t)__cvta_generic_to_shared(p);
}

__device__ __forceinline__ uint32_t pack2(float x, float y) {
    __half2 h = __floats2half2_rn(x, y);
    return *reinterpret_cast<uint32_t*>(&h);
}

// ---------------- prep / elementwise ----------------
__global__ void k_mods(const float* __restrict__ temb, const float* __restrict__ sst) {
    int i = blockIdx.x * 256 + threadIdx.x;
    if (i >= NBATCH * 6 * HID) return;
    int h = i & (HID - 1);
    int r = i >> 11;
    int b = r / 6, mi = r % 6;
    g_mods[i] = sst[mi * HID + h] + temb[b * HID + h];
}

__global__ void k_xmod1(const float* __restrict__ hidden) {
    int i = blockIdx.x * 256 + threadIdx.x;
    if (i >= MROWS * HID) return;
    int h = i & (HID - 1);
    int b = i >> 22;
    const float* md = g_mods + b * 6 * HID;
    g_xmod16[i] = __float2half_rn(hidden[i] * (1.f + md[1 * HID + h]) + md[0 * HID + h]);
}

// direct fp32 -> fp16 convert (vectorized)
__global__ void k_w16(const float4* __restrict__ s, __half* __restrict__ d, int n4) {
    int i = blockIdx.x * 256 + threadIdx.x;
    if (i >= n4) return;
    float4 v = s[i];
    __half2* o = reinterpret_cast<__half2*>(d + (size_t)i * 4);
    o[0] = __floats2half2_rn(v.x, v.y);
    o[1] = __floats2half2_rn(v.z, v.w);
}

// FF weight: interleave rows a0,g0,a1,g1,... while converting
__global__ void k_w16ff(const float* __restrict__ Wff) {
    int i = blockIdx.x * 256 + threadIdx.x;        // over (2*FFD*HID)/4
    if (i >= 2 * FFD * (HID / 4)) return;
    int r = i >> 9;                                 // / (HID/4)
    int c4 = (i & 511) << 2;
    int sr = (r & 1) ? (FFD + (r >> 1)) : (r >> 1);
    float4 v = *reinterpret_cast<const float4*>(Wff + (size_t)sr * HID + c4);
    __half2* o = reinterpret_cast<__half2*>(g_w16ff + (size_t)r * HID + c4);
    o[0] = __floats2half2_rn(v.x, v.y);
    o[1] = __floats2half2_rn(v.z, v.w);
}

// Per-head LayerNorm on fp16 vectors (stats in fp32); one warp per 128-half vector.
// `mul` folds the softmax scale into q.
__global__ void k_ln16(__half* __restrict__ X, float mul) {
    int vec = blockIdx.x * 8 + (threadIdx.x >> 5);
    int lane = threadIdx.x & 31;
    uint2* p = reinterpret_cast<uint2*>(X) + (size_t)vec * 32 + lane;
    uint2 u = *p;
    __half2 h0 = *reinterpret_cast<__half2*>(&u.x);
    __half2 h1 = *reinterpret_cast<__half2*>(&u.y);
    float a = __half2float(h0.x), b = __half2float(h0.y);
    float c = __half2float(h1.x), d = __half2float(h1.y);
    float s = a + b + c + d;
    #pragma unroll
    for (int o = 16; o; o >>= 1) s += __shfl_xor_sync(0xffffffffu, s, o);
    float mean = s * (1.f / 128.f);
    float dx = a - mean, dy = b - mean, dz = c - mean, dw = d - mean;
    float q = dx * dx + dy * dy + dz * dz + dw * dw;
    #pragma unroll
    for (int o = 16; o; o >>= 1) q += __shfl_xor_sync(0xffffffffu, q, o);
    float r = rsqrtf(q * (1.f / 128.f) + 1e-5f) * mul;
    __half2 o0 = __floats2half2_rn(dx * r, dy * r);
    __half2 o1 = __floats2half2_rn(dz * r, dw * r);
    u.x = *reinterpret_cast<uint32_t*>(&o0);
    u.y = *reinterpret_cast<uint32_t*>(&o1);
    *p = u;
}

// ---------------- pipelined fp16 GEMM: C[M,N] = A[M,K] @ W[N,K]^T + bias ----------------
// Tile 128x128, BK=64, 3-stage cp.async, 256 threads (2x4 warps, 64x32 warp tiles),
// 2 CTAs/SM, one __syncthreads per k-tile, fp16 m16n8k16 mma, native ldmatrix b16.
// MODE 0: O-proj   MODE 1: QKV routing (fp16 out)   MODE 2: FF1+GEGLU   MODE 3: FF2+final
#define ROWB 144                    // 64 fp16 = 128B + 16B pad
#define SA_B (128 * ROWB)           // 18432 B per matrix
#define SSTG2 (2 * SA_B)            // 36864 B per stage
#define GEMM_SMEM_BYTES (3 * SSTG2) // 110592 B

template <int MODE>
__global__ __launch_bounds__(256, 2) void gemm_h(
    const __half* __restrict__ A, const __half* __restrict__ W,
    const float* __restrict__ bias0, const float* __restrict__ bias1,
    const float* __restrict__ bias2,
    float* __restrict__ C, int K, const float* __restrict__ resid)
{
    extern __shared__ char smc[];
    const int tid = threadIdx.x;
    constexpr bool MFAST = (MODE == 1 || MODE == 2);
    const int bm = MFAST ? blockIdx.x : blockIdx.y;
    const int bn = MFAST ? blockIdx.y : blockIdx.x;
    const int warp = tid >> 5, lane = tid & 31;
    const int wm = warp >> 2, wn = warp & 3;   // 2x4 warp grid, warp tile 64x32
    const int lg = lane >> 2, lt = lane & 3;
    const uint32_t smem_u = smem_u32(smc);

    const __half* aptr[4]; uint32_t dA[4];
    const __half* wptr[4]; uint32_t dB[4];
    #pragma unroll
    for (int i = 0; i < 4; i++) {
        int idx = tid + i * 256;           // 0..1023
        int r = idx >> 3, c8 = (idx & 7) << 3;
        aptr[i] = A + (size_t)(bm * 128 + r) * K + c8;
        dA[i] = (uint32_t)(r * ROWB + (idx & 7) * 16);
        wptr[i] = W + (size_t)(bn * 128 + r) * K + c8;
        dB[i] = (uint32_t)(SA_B + r * ROWB + (idx & 7) * 16);
    }

    float acc[4][4][4];
    #pragma unroll
    for (int i = 0; i < 4; i++)
        #pragma unroll
        for (int j = 0; j < 4; j++)
            #pragma unroll
            for (int r = 0; r < 4; r++) acc[i][j][r] = 0.f;

    const int nk = K >> 6;

    auto load_stage = [&](int kt, int st) {
        uint32_t base = smem_u + st * SSTG2;
        #pragma unroll
        for (int i = 0; i < 4; i++) cp16(base + dA[i], aptr[i] + kt * 64);
        #pragma unroll
        for (int i = 0; i < 4; i++) cp16(base + dB[i], wptr[i] + kt * 64);
        CP_COMMIT();
    };

    load_stage(0, 0);
    load_stage(1, 1);

    const uint32_t aoff = (uint32_t)((wm * 64 + (lane & 15)) * ROWB + ((lane & 16) ? 16 : 0));
    const uint32_t boff = (uint32_t)(SA_B + (wn * 32 + (lane & 7) + ((lane & 16) ? 8 : 0)) * ROWB +
                                     ((lane & 8) ? 16 : 0));

    int st = 0;
    for (int kt = 0; kt < nk; kt++) {
        CP_WAIT1();
        __syncthreads();
        if (kt + 2 < nk) {
            int nb = st + 2; if (nb >= 3) nb -= 3;
            load_stage(kt + 2, nb);
        } else {
            CP_COMMIT();
        }
        const uint32_t stb = smem_u + st * SSTG2;
        const uint32_t abase = stb + aoff;
        const uint32_t bbase = stb + boff;
        #pragma unroll
        for (int ks = 0; ks < 4; ks++) {            // 4 k-steps of 16
            uint32_t a[4][4];
            #pragma unroll
            for (int mf = 0; mf < 4; mf++)
                ldsm4(a[mf][0], a[mf][1], a[mf][2], a[mf][3],
                      abase + (uint32_t)(mf * 16 * ROWB + ks * 32));
            uint32_t b[4][2];
            #pragma unroll
            for (int nb2 = 0; nb2 < 2; nb2++) {     // each x4 covers 16 n
                uint32_t t0, t1, t2, t3;
                ldsm4(t0, t1, t2, t3, bbase + (uint32_t)(nb2 * 16 * ROWB + ks * 32));
                b[2 * nb2][0]     = t0;  b[2 * nb2][1]     = t1;
                b[2 * nb2 + 1][0] = t2;  b[2 * nb2 + 1][1] = t3;
            }
            #pragma unroll
            for (int mf = 0; mf < 4; mf++)
                #pragma unroll
                for (int nf = 0; nf < 4; nf++)
                    mma16(acc[mf][nf], a[mf], b[nf][0], b[nf][1]);
        }
        st = (st == 2) ? 0 : st + 1;
    }

    // ---------------- epilogue ----------------
    #pragma unroll
    for (int mf = 0; mf < 4; mf++) {
        #pragma unroll
        for (int nf = 0; nf < 4; nf++) {
            int row0 = bm * 128 + wm * 64 + mf * 16 + lg;
            int col0 = bn * 128 + wn * 32 + nf * 8 + lt * 2;
            float b0, b1;
            if (MODE == 1) {
                int seg = col0 >> 11;
                const float* bs = (seg == 0) ? bias0 : (seg == 1) ? bias1 : bias2;
                int colr = col0 & (HID - 1);
                b0 = bs[colr]; b1 = bs[colr + 1];
            } else if (MODE == 2) {
                int f = col0 >> 1;
                b0 = bias0[f]; b1 = bias0[FFD + f];
            } else {
                b0 = bias0[col0]; b1 = bias0[col0 + 1];
            }
            #pragma unroll
            for (int rr = 0; rr < 2; rr++) {
                int row = row0 + rr * 8;
                float v0 = acc[mf][nf][rr * 2 + 0] + b0;
                float v1 = acc[mf][nf][rr * 2 + 1] + b1;
                if (MODE == 1) {
                    int seg = col0 >> 11;
                    int colr = col0 & (HID - 1);
                    __half* dst = (seg == 0) ? g_q16 : (seg == 1) ? g_k16 : g_v16;
                    size_t o = (size_t)row * HID + colr;
                    *reinterpret_cast<__half2*>(&dst[o]) = __floats2half2_rn(v0, v1);
                } else if (MODE == 0) {
                    int b = row >> 11;
                    const float* md = g_mods + b * 6 * HID;
                    size_t o = (size_t)row * HID + col0;
                    float h0 = resid[o]     + md[2 * HID + col0]     * v0;
                    float h1 = resid[o + 1] + md[2 * HID + col0 + 1] * v1;
                    g_h2[o] = h0; g_h2[o + 1] = h1;
                    float x0 = h0 * (1.f + md[4 * HID + col0])     + md[3 * HID + col0];
                    float x1 = h1 * (1.f + md[4 * HID + col0 + 1]) + md[3 * HID + col0 + 1];
                    *reinterpret_cast<__half2*>(&g_xmod16[o]) = __floats2half2_rn(x0, x1);
                } else if (MODE == 2) {
                    float g = v1;
                    float gl = 0.5f * g * (1.f + tanhf(0.7978845608028654f * (g + 0.044715f * g * g * g)));
                    int f = col0 >> 1;
                    g_ffg16[(size_t)row * FFD + f] = __float2half_rn(v0 * gl);
                } else { // MODE == 3
                    int b = row >> 11;
                    size_t o = (size_t)row * HID + col0;
                    C[o]     = resid[o]     + g_mods[b * 6 * HID + 5 * HID + col0]     * v0;
                    C[o + 1] = resid[o + 1] + g_mods[b * 6 * HID + 5 * HID + col0 + 1] * v1;
                }
            }
        }
    }
}

// ---------------- fp16 flash attention (m16n8k16, register-resident P) ----------------
// Per CTA: 64 q-rows, 4 warps (16 q-rows each). K/V tiles 64x128 fp16, single-buffered.
// QK^T: ldmatrix (K row-major [n][k]); PV: ldmatrix.trans (V row-major [k][n]).
#define AST 136                     // halves per smem row
#define ASTB 272                    // bytes per smem row (== 16 mod 128 -> conflict-free)
#define ATT_SMEM_BYTES (3 * 64 * ASTB)   // Q + K + V tiles = 52224 B

__global__ __launch_bounds__(128, 2) void attn_h(
    const __half* __restrict__ Q, const __half* __restrict__ Kg,
    const __half* __restrict__ V, __half* __restrict__ Og)
{
    extern __shared__ __half hsm[];
    const uint32_t sQ = smem_u32(hsm);
    const uint32_t sK = sQ + 64 * ASTB;
    const uint32_t sV = sK + 64 * ASTB;

    const int tid = threadIdx.x, warp = tid >> 5, lane = tid & 31;
    const int lg = lane >> 2, lt = lane & 3;
    const int qt = blockIdx.x, bh = blockIdx.y;
    const int b = bh >> 4, h = bh & 15;
    const int m_base = warp * 16;

    const size_t base = (size_t)b * SLEN * HID + (size_t)h * HD;
    const __half* Qp = Q + base + (size_t)qt * 64 * HID;
    const __half* Kp = Kg + base;
    const __half* Vp = V + base;

    // load Q tile: 64 rows x 128 halves = 1024 16B chunks
    #pragma unroll
    for (int i = 0; i < 8; i++) {
        int idx = tid + i * 128;
        int r = idx >> 4, c = idx & 15;
        cp16(sQ + (uint32_t)(r * ASTB + c * 16), Qp + (size_t)r * HID + c * 8);
    }
    CP_COMMIT();

    float o[16][4];
    #pragma unroll
    for (int i = 0; i < 16; i++)
        #pragma unroll
        for (int j = 0; j < 4; j++) o[i][j] = 0.f;
    float m0 = -INFINITY, m1 = -INFINITY, l0 = 0.f, l1 = 0.f;

    // fragment base offsets
    const uint32_t aoff = sQ + (uint32_t)((m_base + (lane & 15)) * ASTB + ((lane & 16) ? 16 : 0));
    const uint32_t koff = sK + (uint32_t)(((lane & 7) + ((lane & 16) ? 8 : 0)) * ASTB +
                                          ((lane & 8) ? 16 : 0));
    const uint32_t voff = sV + (uint32_t)((lane & 15) * ASTB + ((lane & 16) ? 16 : 0));

    for (int kt = 0; kt < SLEN / 64; kt++) {
        __syncthreads();           // prev iteration done reading K/V tiles
        #pragma unroll
        for (int i = 0; i < 8; i++) {
            int idx = tid + i * 128;
            int r = idx >> 4, c = idx & 15;
            const size_t go = (size_t)(kt * 64 + r) * HID + c * 8;
            cp16(sK + (uint32_t)(r * ASTB + c * 16), Kp + go);
            cp16(sV + (uint32_t)(r * ASTB + c * 16), Vp + go);
        }
        CP_COMMIT_WAIT0();
        __syncthreads();

        // ---- S = Q @ K^T ----
        float s_acc[8][4];
        #pragma unroll
        for (int nf = 0; nf < 8; nf++)
            #pragma unroll
            for (int j = 0; j < 4; j++) s_acc[nf][j] = 0.f;

        #pragma unroll
        for (int ks = 0; ks < 8; ks++) {           // 8 k-steps of 16 over d=128
            uint32_t a[4];
            ldsm4(a[0], a[1], a[2], a[3], aoff + (uint32_t)(ks * 32));
            #pragma unroll
            for (int n2 = 0; n2 < 4; n2++) {       // 4 groups of 16 keys
                uint32_t t0, t1, t2, t3;
                ldsm4(t0, t1, t2, t3, koff + (uint32_t)(n2 * 16 * ASTB + ks * 32));
                mma16(s_acc[2 * n2],     a, t0, t1);
                mma16(s_acc[2 * n2 + 1], a, t2, t3);
            }
        }

        // ---- online softmax ----
        float t0v = -INFINITY, t1v = -INFINITY;
        #pragma unroll
        for (int nf = 0; nf < 8; nf++) {
            t0v = fmaxf(t0v, fmaxf(s_acc[nf][0], s_acc[nf][1]));
            t1v = fmaxf(t1v, fmaxf(s_acc[nf][2], s_acc[nf][3]));
        }
        t0v = fmaxf(t0v, __shfl_xor_sync(0xffffffffu, t0v, 1));
        t0v = fmaxf(t0v, __shfl_xor_sync(0xffffffffu, t0v, 2));
        t1v = fmaxf(t1v, __shfl_xor_sync(0xffffffffu, t1v, 1));
        t1v = fmaxf(t1v, __shfl_xor_sync(0xffffffffu, t1v, 2));
        float nm0 = fmaxf(m0, t0v), nm1 = fmaxf(m1, t1v);
        float al0 = __expf(m0 - nm0), al1 = __expf(m1 - nm1);
        float ps0 = 0.f, ps1 = 0.f;
        #pragma unroll
        for (int nf = 0; nf < 8; nf++) {
            s_acc[nf][0] = __expf(s_acc[nf][0] - nm0);
            s_acc[nf][1] = __expf(s_acc[nf][1] - nm0);
            s_acc[nf][2] = __expf(s_acc[nf][2] - nm1);
            s_acc[nf][3] = __expf(s_acc[nf][3] - nm1);
            ps0 += s_acc[nf][0] + s_acc[nf][1];
            ps1 += s_acc[nf][2] + s_acc[nf][3];
        }
        ps0 += __shfl_xor_sync(0xffffffffu, ps0, 1);
        ps0 += __shfl_xor_sync(0xffffffffu, ps0, 2);
        ps1 += __shfl_xor_sync(0xffffffffu, ps1, 1);
        ps1 += __shfl_xor_sync(0xffffffffu, ps1, 2);
        l0 = l0 * al0 + ps0;  l1 = l1 * al1 + ps1;
        m0 = nm0;  m1 = nm1;
        #pragma unroll
        for (int nf = 0; nf < 16; nf++) {
            o[nf][0] *= al0; o[nf][1] *= al0; o[nf][2] *= al1; o[nf][3] *= al1;
        }

        // ---- O += P @ V  (P register-direct; V via ldmatrix.trans) ----
        #pragma unroll
        for (int ks = 0; ks < 4; ks++) {           // 4 k-steps of 16 over s=64
            uint32_t pa[4];
            pa[0] = pack2(s_acc[2 * ks][0],     s_acc[2 * ks][1]);
            pa[1] = pack2(s_acc[2 * ks][2],     s_acc[2 * ks][3]);
            pa[2] = pack2(s_acc[2 * ks + 1][0], s_acc[2 * ks + 1][1]);
            pa[3] = pack2(s_acc[2 * ks + 1][2], s_acc[2 * ks + 1][3]);
            #pragma unroll
            for (int n2 = 0; n2 < 8; n2++) {       // 8 groups of 16 d
                uint32_t t0, t1, t2, t3;
                ldsm4t(t0, t1, t2, t3, voff + (uint32_t)(ks * 16 * ASTB + n2 * 32));
                mma16(o[2 * n2],     pa, t0, t1);
                mma16(o[2 * n2 + 1], pa, t2, t3);
            }
        }
    }

    float il0 = 1.f / l0, il1 = 1.f / l1;
    int row0 = qt * 64 + m_base + lg;
    #pragma unroll
    for (int nf = 0; nf < 16; nf++) {
        size_t oi = (size_t)(b * SLEN + row0) * HID + h * HD + nf * 8 + lt * 2;
        *reinterpret_cast<__half2*>(&Og[oi]) =
            __floats2half2_rn(o[nf][0] * il0, o[nf][1] * il0);
        *reinterpret_cast<__half2*>(&Og[oi + (size_t)8 * HID]) =
            __floats2half2_rn(o[nf][2] * il1, o[nf][3] * il1);
    }
}

// ---------------- launch ----------------
extern "C" void kernel_launch(void* const* d_in, const int* in_sizes, int n_in,
                              void* d_out, int out_size) {
    const float* hidden = (const float*)d_in[0];
    const float* temb   = (const float*)d_in[1];
    const float* Wq = (const float*)d_in[2];  const float* bq = (const float*)d_in[3];
    const float* Wk = (const float*)d_in[4];  const float* bk = (const float*)d_in[5];
    const float* Wv = (const float*)d_in[6];  const float* bv = (const float*)d_in[7];
    const float* Wo = (const float*)d_in[8];  const float* bo = (const float*)d_in[9];
    const float* Wff = (const float*)d_in[10]; const float* bff = (const float*)d_in[11];
    const float* Wfo = (const float*)d_in[12]; const float* bfo = (const float*)d_in[13];
    const float* sst = (const float*)d_in[14];
    float* out = (float*)d_out;

    void *p_xmod, *p_q, *p_k, *p_v, *p_attn, *p_h2, *p_ffg;
    void *p_wqkv, *p_wo, *p_wff, *p_wfo;
    cudaGetSymbolAddress(&p_xmod, g_xmod16);
    cudaGetSymbolAddress(&p_q, g_q16);
    cudaGetSymbolAddress(&p_k, g_k16);
    cudaGetSymbolAddress(&p_v, g_v16);
    cudaGetSymbolAddress(&p_attn, g_attn16);
    cudaGetSymbolAddress(&p_h2, g_h2);
    cudaGetSymbolAddress(&p_ffg, g_ffg16);
    cudaGetSymbolAddress(&p_wqkv, g_w16qkv);
    cudaGetSymbolAddress(&p_wo, g_w16o);
    cudaGetSymbolAddress(&p_wff, g_w16ff);
    cudaGetSymbolAddress(&p_wfo, g_w16fo);
    __half* xmod = (__half*)p_xmod;
    __half* q = (__half*)p_q; __half* k = (__half*)p_k; __half* v = (__half*)p_v;
    __half* attn = (__half*)p_attn; float* h2 = (float*)p_h2; __half* ffg = (__half*)p_ffg;
    __half* wqkv = (__half*)p_wqkv; __half* wo = (__half*)p_wo;
    __half* wff = (__half*)p_wff; __half* wfo = (__half*)p_wfo;

    cudaFuncSetAttribute(attn_h, cudaFuncAttributeMaxDynamicSharedMemorySize, ATT_SMEM_BYTES);
    cudaFuncSetAttribute(gemm_h<0>, cudaFuncAttributeMaxDynamicSharedMemorySize, GEMM_SMEM_BYTES);
    cudaFuncSetAttribute(gemm_h<1>, cudaFuncAttributeMaxDynamicSharedMemorySize, GEMM_SMEM_BYTES);
    cudaFuncSetAttribute(gemm_h<2>, cudaFuncAttributeMaxDynamicSharedMemorySize, GEMM_SMEM_BYTES);
    cudaFuncSetAttribute(gemm_h<3>, cudaFuncAttributeMaxDynamicSharedMemorySize, GEMM_SMEM_BYTES);

    // prep: modulation + fp16 weight conversion (routing baked in)
    k_mods<<<(NBATCH * 6 * HID + 255) / 256, 256>>>(temb, sst);
    k_xmod1<<<(MROWS * HID + 255) / 256, 256>>>(hidden);
    {
        int n4h = HID * HID / 4;
        k_w16<<<n4h / 256, 256>>>((const float4*)Wq, wqkv, n4h);
        k_w16<<<n4h / 256, 256>>>((const float4*)Wk, wqkv + (size_t)HID * HID, n4h);
        k_w16<<<n4h / 256, 256>>>((const float4*)Wv, wqkv + (size_t)2 * HID * HID, n4h);
        k_w16<<<n4h / 256, 256>>>((const float4*)Wo, wo, n4h);
        k_w16ff<<<(2 * FFD * (HID / 4)) / 256, 256>>>(Wff);
        int n4o = HID * FFD / 4;
        k_w16<<<n4o / 256, 256>>>((const float4*)Wfo, wfo, n4o);
    }

    // fused QKV GEMM: [4096, 6144] (bm-fastest raster), fp16 outputs
    gemm_h<1><<<dim3(MROWS / 128, 3 * HID / 128), 256, GEMM_SMEM_BYTES>>>(
        xmod, wqkv, bq, bk, bv, nullptr, HID, nullptr);

    k_ln16<<<(MROWS * NHEADS) / 8, 256>>>(q, 0.08838834764831845f);  // 1/sqrt(128)
    k_ln16<<<(MROWS * NHEADS) / 8, 256>>>(k, 1.0f);

    attn_h<<<dim3(SLEN / 64, NBATCH * NHEADS), 128, ATT_SMEM_BYTES>>>(q, k, v, attn);

    // O-proj + residual + mlp-modulation (bn-fastest)
    gemm_h<0><<<dim3(HID / 128, MROWS / 128), 256, GEMM_SMEM_BYTES>>>(
        attn, wo, bo, nullptr, nullptr, nullptr, HID, hidden);

    // FF1 + GEGLU (bm-fastest)
    gemm_h<2><<<dim3(MROWS / 128, 2 * FFD / 128), 256, GEMM_SMEM_BYTES>>>(
        xmod, wff, bff, nullptr, nullptr, nullptr, HID, nullptr);

    // FF2 + final residual (bn-fastest)
    gemm_h<3><<<dim3(HID / 128, MROWS / 128), 256, GEMM_SMEM_BYTES>>>(
        ffg, wfo, bfo, nullptr, nullptr, out, FFD, h2);
}